// round 3
// baseline (speedup 1.0000x reference)
#include <cuda_runtime.h>

#define NN 50000
#define NE 800000
#define DD 128

// ---------------- scratch (no allocs allowed -> device globals) ----------------
__device__ int   g_deg[NN];
__device__ int   g_off[NN];
__device__ int   g_cur[NN];
__device__ int   g_adj[NE];
__device__ int   g_bsum[32];
__device__ int   g_is32;
__device__ __align__(16) float g_mean[(size_t)NN * DD];
__device__ __align__(16) float g_h1[(size_t)NN * DD];
__device__ __align__(16) float g_Wt1[2 * DD * DD];  // [k][j]; k<128: W1l, k>=128: W1r
__device__ __align__(16) float g_Wt2[2 * DD * DD];

// ---------------- edge dtype detection ----------------
// Reference declares int64, but JAX x64 is off by default -> likely int32.
// Valid node ids < 50000; int32 pairs read as int64 give values >= 2^32-scale.
__global__ void k_detect(const unsigned long long* __restrict__ ei) {
    if (threadIdx.x == 0) {
        int bad = 0;
        #pragma unroll
        for (int i = 0; i < 16; i++)
            if (ei[i] >= (unsigned long long)NN) bad = 1;
        g_is32 = bad;
    }
}

__device__ __forceinline__ int load_src(const void* ei, int e) {
    return g_is32 ? ((const int*)ei)[e] : (int)((const long long*)ei)[e];
}
__device__ __forceinline__ int load_dst(const void* ei, int e) {
    return g_is32 ? ((const int*)ei)[NE + e] : (int)((const long long*)ei)[NE + e];
}

// ---------------- CSR build ----------------
__global__ void k_zero() {
    int i = blockIdx.x * blockDim.x + threadIdx.x;
    if (i < NN) g_deg[i] = 0;
}

__global__ void k_hist(const void* __restrict__ ei) {
    int e = blockIdx.x * blockDim.x + threadIdx.x;
    if (e < NE) {
        int dst = load_dst(ei, e);
        if ((unsigned)dst < (unsigned)NN) atomicAdd(&g_deg[dst], 1);
    }
}

// block scan: 25 blocks x 1024 threads x 2 elems
__global__ void k_scan1() {
    __shared__ int sc[1024];
    int t = threadIdx.x;
    int base = blockIdx.x * 2048;
    int i0 = base + 2 * t, i1 = i0 + 1;
    int a = (i0 < NN) ? g_deg[i0] : 0;
    int b = (i1 < NN) ? g_deg[i1] : 0;
    sc[t] = a + b;
    __syncthreads();
    #pragma unroll
    for (int off = 1; off < 1024; off <<= 1) {
        int v = (t >= off) ? sc[t - off] : 0;
        __syncthreads();
        sc[t] += v;
        __syncthreads();
    }
    int excl = sc[t] - (a + b);
    if (i0 < NN) g_off[i0] = excl;
    if (i1 < NN) g_off[i1] = excl + a;
    if (t == 1023) g_bsum[blockIdx.x] = sc[t];
}

__global__ void k_scan2(int nb) {
    if (threadIdx.x == 0) {
        int s = 0;
        for (int i = 0; i < nb; i++) { int v = g_bsum[i]; g_bsum[i] = s; s += v; }
    }
}

__global__ void k_scan3() {
    int i = blockIdx.x * blockDim.x + threadIdx.x;
    if (i < NN) {
        int o = g_off[i] + g_bsum[i >> 11];
        g_off[i] = o;
        g_cur[i] = o;
    }
}

__global__ void k_scatter(const void* __restrict__ ei) {
    int e = blockIdx.x * blockDim.x + threadIdx.x;
    if (e < NE) {
        int dst = load_dst(ei, e);
        int src = load_src(ei, e);
        if ((unsigned)dst < (unsigned)NN && (unsigned)src < (unsigned)NN) {
            int pos = atomicAdd(&g_cur[dst], 1);
            if ((unsigned)pos < (unsigned)NE) g_adj[pos] = src;
        }
    }
}

// ---------------- weight transpose prep ----------------
__global__ void k_wprep(const float* __restrict__ W1l, const float* __restrict__ W1r,
                        const float* __restrict__ W2l, const float* __restrict__ W2r) {
    int id = blockIdx.x * blockDim.x + threadIdx.x;
    if (id >= DD * DD) return;
    int k = id / DD, j = id % DD;
    g_Wt1[k * DD + j]        = W1l[j * DD + k];
    g_Wt1[(DD + k) * DD + j] = W1r[j * DD + k];
    g_Wt2[k * DD + j]        = W2l[j * DD + k];
    g_Wt2[(DD + k) * DD + j] = W2r[j * DD + k];
}

// ---------------- mean aggregation: one warp per node ----------------
template <int LAYER>
__global__ void __launch_bounds__(256) k_agg(const float* __restrict__ x) {
    const float* feat = (LAYER == 1) ? x : (const float*)g_h1;
    int warp = (blockIdx.x * blockDim.x + threadIdx.x) >> 5;
    int lane = threadIdx.x & 31;
    if (warp >= NN) return;
    int beg = g_off[warp];
    int d   = g_deg[warp];
    float4 acc = make_float4(0.f, 0.f, 0.f, 0.f);
    for (int b = 0; b < d; b += 32) {
        int m  = min(32, d - b);
        int sl = (lane < m) ? g_adj[beg + b + lane] : 0;
        #pragma unroll 4
        for (int j = 0; j < m; j++) {
            int s = __shfl_sync(0xffffffffu, sl, j);
            const float4 v = __ldg((const float4*)(feat + (size_t)s * DD + lane * 4));
            acc.x += v.x; acc.y += v.y; acc.z += v.z; acc.w += v.w;
        }
    }
    float inv = 1.0f / (float)max(d, 1);
    acc.x *= inv; acc.y *= inv; acc.z *= inv; acc.w *= inv;
    *(float4*)(g_mean + (size_t)warp * DD + lane * 4) = acc;
}

// ---------------- fused GEMM: out = mean@Wl^T + h@Wr^T + b (+ReLU [+LN]) ----------------
// 128 threads (tx 0..15 x ty 0..7), block tile 64 rows x 128 cols, 8x8 per thread.
// K = 256 (two halves of 128), streamed in BK=32 chunks through static smem (<=48KB).
// Packed fp32x2 FMA for 2x FFMA throughput.
#define BK 32
#define ASTRIDE 33   // pad so rows hit distinct banks

template <int LAYER>
__global__ void __launch_bounds__(128) k_gemm(
    const float* __restrict__ xin, const float* __restrict__ bias,
    const float* __restrict__ lnw, const float* __restrict__ lnb,
    float* __restrict__ outp)
{
    __shared__ float Ws[BK * DD];        // [k][j], 16 KB
    __shared__ float As[64 * ASTRIDE];   // [row][k] padded, 8.4 KB

    const int tid = threadIdx.x;
    const int tx = tid & 15, ty = tid >> 4;
    const int row0 = blockIdx.x * 64;
    const float* Ah = (LAYER == 1) ? xin : (const float*)g_h1;
    const float* Wt = (LAYER == 1) ? (const float*)g_Wt1 : (const float*)g_Wt2;
    float* dst = (LAYER == 1) ? (float*)g_h1 : outp;

    unsigned long long acc[8][4];
    #pragma unroll
    for (int r = 0; r < 8; r++)
        #pragma unroll
        for (int p = 0; p < 4; p++) acc[r][p] = 0ULL;

    for (int half = 0; half < 2; half++) {
        const float* A = half ? Ah : (const float*)g_mean;
        for (int kc = 0; kc < 4; kc++) {
            const float* W = Wt + half * DD * DD + (kc * BK) * DD;
            const int kofs = kc * BK;
            __syncthreads();
            #pragma unroll
            for (int i = tid * 4; i < BK * DD; i += 512)
                *(float4*)(Ws + i) = *(const float4*)(W + i);
            #pragma unroll
            for (int i = tid * 4; i < 64 * BK; i += 512) {
                int r = i >> 5, c = i & 31;
                int gr = row0 + r;
                float4 v = make_float4(0.f, 0.f, 0.f, 0.f);
                if (gr < NN) v = *(const float4*)(A + (size_t)gr * DD + kofs + c);
                float* p = As + r * ASTRIDE + c;
                p[0] = v.x; p[1] = v.y; p[2] = v.z; p[3] = v.w;
            }
            __syncthreads();
            #pragma unroll 4
            for (int k = 0; k < BK; k++) {
                const ulonglong2 wv0 = *(const ulonglong2*)(Ws + k * DD + tx * 8);
                const ulonglong2 wv1 = *(const ulonglong2*)(Ws + k * DD + tx * 8 + 4);
                const unsigned long long w0 = wv0.x, w1 = wv0.y, w2 = wv1.x, w3 = wv1.y;
                #pragma unroll
                for (int r = 0; r < 8; r++) {
                    float a = As[(ty * 8 + r) * ASTRIDE + k];
                    unsigned long long ad;
                    asm("mov.b64 %0, {%1, %1};" : "=l"(ad) : "f"(a));
                    asm("fma.rn.f32x2 %0, %1, %2, %0;" : "+l"(acc[r][0]) : "l"(ad), "l"(w0));
                    asm("fma.rn.f32x2 %0, %1, %2, %0;" : "+l"(acc[r][1]) : "l"(ad), "l"(w1));
                    asm("fma.rn.f32x2 %0, %1, %2, %0;" : "+l"(acc[r][2]) : "l"(ad), "l"(w2));
                    asm("fma.rn.f32x2 %0, %1, %2, %0;" : "+l"(acc[r][3]) : "l"(ad), "l"(w3));
                }
            }
        }
    }

    // epilogue: bias + relu (+ LayerNorm for layer 2), all in registers
    float bv[8];
    #pragma unroll
    for (int p = 0; p < 8; p++) bv[p] = bias[tx * 8 + p];

    float4 lw0, lw1, lb0, lb1;
    if (LAYER == 2) {
        lw0 = *(const float4*)(lnw + tx * 8);
        lw1 = *(const float4*)(lnw + tx * 8 + 4);
        lb0 = *(const float4*)(lnb + tx * 8);
        lb1 = *(const float4*)(lnb + tx * 8 + 4);
    }

    #pragma unroll
    for (int r = 0; r < 8; r++) {
        float v[8];
        #pragma unroll
        for (int p = 0; p < 4; p++) {
            float lo, hi;
            asm("mov.b64 {%0, %1}, %2;" : "=f"(lo), "=f"(hi) : "l"(acc[r][p]));
            v[2 * p]     = fmaxf(lo + bv[2 * p], 0.f);
            v[2 * p + 1] = fmaxf(hi + bv[2 * p + 1], 0.f);
        }
        int gr = row0 + ty * 8 + r;
        if (LAYER == 2) {
            // row lives in 16 contiguous lanes of this half-warp
            float s = 0.f, sq = 0.f;
            #pragma unroll
            for (int p = 0; p < 8; p++) { s += v[p]; sq += v[p] * v[p]; }
            #pragma unroll
            for (int o = 8; o > 0; o >>= 1) {
                s  += __shfl_xor_sync(0xffffffffu, s, o);
                sq += __shfl_xor_sync(0xffffffffu, sq, o);
            }
            float mu  = s * (1.0f / DD);
            float var = sq * (1.0f / DD) - mu * mu;
            float rs  = rsqrtf(var + 1e-5f);
            if (gr < NN) {
                float4 o0, o1;
                o0.x = (v[0] - mu) * rs * lw0.x + lb0.x;
                o0.y = (v[1] - mu) * rs * lw0.y + lb0.y;
                o0.z = (v[2] - mu) * rs * lw0.z + lb0.z;
                o0.w = (v[3] - mu) * rs * lw0.w + lb0.w;
                o1.x = (v[4] - mu) * rs * lw1.x + lb1.x;
                o1.y = (v[5] - mu) * rs * lw1.y + lb1.y;
                o1.z = (v[6] - mu) * rs * lw1.z + lb1.z;
                o1.w = (v[7] - mu) * rs * lw1.w + lb1.w;
                *(float4*)(dst + (size_t)gr * DD + tx * 8)     = o0;
                *(float4*)(dst + (size_t)gr * DD + tx * 8 + 4) = o1;
            }
        } else {
            if (gr < NN) {
                *(float4*)(dst + (size_t)gr * DD + tx * 8) =
                    make_float4(v[0], v[1], v[2], v[3]);
                *(float4*)(dst + (size_t)gr * DD + tx * 8 + 4) =
                    make_float4(v[4], v[5], v[6], v[7]);
            }
        }
    }
}

// ---------------- launch: kernel launches ONLY, no host CUDA APIs ----------------
extern "C" void kernel_launch(void* const* d_in, const int* in_sizes, int n_in,
                              void* d_out, int out_size) {
    const float* x   = (const float*)d_in[0];
    const void*  ei  = d_in[1];
    const float* W1l = (const float*)d_in[2];
    const float* b1l = (const float*)d_in[3];
    const float* W1r = (const float*)d_in[4];
    const float* W2l = (const float*)d_in[5];
    const float* b2l = (const float*)d_in[6];
    const float* W2r = (const float*)d_in[7];
    const float* lnw = (const float*)d_in[8];
    const float* lnb = (const float*)d_in[9];
    float* out = (float*)d_out;

    const int scan_blocks = (NN + 2047) / 2048;  // 25

    k_detect<<<1, 32>>>((const unsigned long long*)ei);
    k_zero<<<(NN + 255) / 256, 256>>>();
    k_hist<<<(NE + 255) / 256, 256>>>(ei);
    k_scan1<<<scan_blocks, 1024>>>();
    k_scan2<<<1, 32>>>(scan_blocks);
    k_scan3<<<(NN + 255) / 256, 256>>>();
    k_scatter<<<(NE + 255) / 256, 256>>>(ei);
    k_wprep<<<(DD * DD + 255) / 256, 256>>>(W1l, W1r, W2l, W2r);

    // layer 1
    k_agg<1><<<(NN * 32 + 255) / 256, 256>>>(x);
    k_gemm<1><<<(NN + 63) / 64, 128>>>(x, b1l, nullptr, nullptr, out);

    // layer 2 (+ LayerNorm)
    k_agg<2><<<(NN * 32 + 255) / 256, 256>>>(x);
    k_gemm<2><<<(NN + 63) / 64, 128>>>(x, b2l, lnw, lnb, out);
}

// round 6
// speedup vs baseline: 1.0168x; 1.0168x over previous
#include <cuda_runtime.h>
#include <cuda_bf16.h>
#include <cstdint>

#define NN 50000
#define NE 800000
#define DD 128

// tcgen05 is only legal on arch-specific targets (sm_103a / sm_100a).
// The harness also compiles a plain compute_103 pass -> give it a stub body.
#if !defined(__CUDA_ARCH__) || defined(__CUDA_ARCH_FEAT_SM103_ALL) || \
    defined(__CUDA_ARCH_FEAT_SM100_ALL) || defined(__CUDA_ARCH_SPECIFIC__)
#define TC5 1
#else
#define TC5 0
#endif

// ---------------- scratch (no allocs -> device globals) ----------------
__device__ int   g_deg[NN];
__device__ int   g_off[NN];
__device__ int   g_cur[NN];
__device__ int   g_adj[NE];
__device__ int   g_bsum[32];
__device__ int   g_is32;
__device__ __align__(16) float          g_h1[(size_t)NN * DD];
__device__ __align__(16) __nv_bfloat16  g_xhi[(size_t)NN * DD];
__device__ __align__(16) __nv_bfloat16  g_xlo[(size_t)NN * DD];
__device__ __align__(16) __nv_bfloat16  g_mhi[(size_t)NN * DD];
__device__ __align__(16) __nv_bfloat16  g_mlo[(size_t)NN * DD];
__device__ __align__(16) __nv_bfloat16  g_h1hi[(size_t)NN * DD];
__device__ __align__(16) __nv_bfloat16  g_h1lo[(size_t)NN * DD];
__device__ __align__(16) __nv_bfloat16  g_B1hi[DD * 2 * DD];  // [j][k] k-major, K=256
__device__ __align__(16) __nv_bfloat16  g_B1lo[DD * 2 * DD];
__device__ __align__(16) __nv_bfloat16  g_B2hi[DD * 2 * DD];
__device__ __align__(16) __nv_bfloat16  g_B2lo[DD * 2 * DD];

// ---------------- small helpers ----------------
__device__ __forceinline__ uint32_t s2u32(const void* p) {
    uint32_t a;
    asm("{ .reg .u64 t; cvta.to.shared.u64 t, %1; cvt.u32.u64 %0, t; }" : "=r"(a) : "l"(p));
    return a;
}
__device__ __forceinline__ unsigned pk2(__nv_bfloat16 a, __nv_bfloat16 b) {
    unsigned short ua = *(unsigned short*)&a, ub = *(unsigned short*)&b;
    return (unsigned)ua | ((unsigned)ub << 16);
}
__device__ __forceinline__ void split1(float v, __nv_bfloat16& h, __nv_bfloat16& l) {
    h = __float2bfloat16_rn(v);
    l = __float2bfloat16_rn(v - __bfloat162float(h));
}

// ---------------- edge dtype detection (JAX x64-off -> int32 likely) ----------------
__global__ void k_detect(const unsigned long long* __restrict__ ei) {
    if (threadIdx.x == 0) {
        int bad = 0;
        #pragma unroll
        for (int i = 0; i < 16; i++)
            if (ei[i] >= (unsigned long long)NN) bad = 1;
        g_is32 = bad;
    }
}
__device__ __forceinline__ int load_src(const void* ei, int e) {
    return g_is32 ? ((const int*)ei)[e] : (int)((const long long*)ei)[e];
}
__device__ __forceinline__ int load_dst(const void* ei, int e) {
    return g_is32 ? ((const int*)ei)[NE + e] : (int)((const long long*)ei)[NE + e];
}

// ---------------- CSR build ----------------
__global__ void k_zero() {
    int i = blockIdx.x * blockDim.x + threadIdx.x;
    if (i < NN) g_deg[i] = 0;
}
__global__ void k_hist(const void* __restrict__ ei) {
    int e = blockIdx.x * blockDim.x + threadIdx.x;
    if (e < NE) {
        int dst = load_dst(ei, e);
        if ((unsigned)dst < (unsigned)NN) atomicAdd(&g_deg[dst], 1);
    }
}
__global__ void k_scan1() {
    __shared__ int sc[1024];
    int t = threadIdx.x;
    int base = blockIdx.x * 2048;
    int i0 = base + 2 * t, i1 = i0 + 1;
    int a = (i0 < NN) ? g_deg[i0] : 0;
    int b = (i1 < NN) ? g_deg[i1] : 0;
    sc[t] = a + b;
    __syncthreads();
    #pragma unroll
    for (int off = 1; off < 1024; off <<= 1) {
        int v = (t >= off) ? sc[t - off] : 0;
        __syncthreads();
        sc[t] += v;
        __syncthreads();
    }
    int excl = sc[t] - (a + b);
    if (i0 < NN) g_off[i0] = excl;
    if (i1 < NN) g_off[i1] = excl + a;
    if (t == 1023) g_bsum[blockIdx.x] = sc[t];
}
__global__ void k_scan2(int nb) {
    if (threadIdx.x == 0) {
        int s = 0;
        for (int i = 0; i < nb; i++) { int v = g_bsum[i]; g_bsum[i] = s; s += v; }
    }
}
__global__ void k_scan3() {
    int i = blockIdx.x * blockDim.x + threadIdx.x;
    if (i < NN) {
        int o = g_off[i] + g_bsum[i >> 11];
        g_off[i] = o;
        g_cur[i] = o;
    }
}
__global__ void k_scatter(const void* __restrict__ ei) {
    int e = blockIdx.x * blockDim.x + threadIdx.x;
    if (e < NE) {
        int dst = load_dst(ei, e);
        int src = load_src(ei, e);
        if ((unsigned)dst < (unsigned)NN && (unsigned)src < (unsigned)NN) {
            int pos = atomicAdd(&g_cur[dst], 1);
            if ((unsigned)pos < (unsigned)NE) g_adj[pos] = src;
        }
    }
}

// ---------------- x -> bf16 hi/lo ----------------
__global__ void k_convx(const float* __restrict__ x) {
    int i = blockIdx.x * blockDim.x + threadIdx.x;   // float4 index
    if (i >= NN * (DD / 4)) return;
    float4 v = ((const float4*)x)[i];
    __nv_bfloat16 h0, h1, h2, h3, l0, l1, l2, l3;
    split1(v.x, h0, l0); split1(v.y, h1, l1); split1(v.z, h2, l2); split1(v.w, h3, l3);
    ((uint2*)g_xhi)[i] = make_uint2(pk2(h0, h1), pk2(h2, h3));
    ((uint2*)g_xlo)[i] = make_uint2(pk2(l0, l1), pk2(l2, l3));
}

// ---------------- weight prep: B[j][k] = k<128 ? Wl[j][k] : Wr[j][k-128], hi/lo ----------------
__global__ void k_wprep(const float* __restrict__ W1l, const float* __restrict__ W1r,
                        const float* __restrict__ W2l, const float* __restrict__ W2r) {
    int id = blockIdx.x * blockDim.x + threadIdx.x;
    if (id >= DD * 2 * DD) return;
    int j = id >> 8, k = id & 255;
    float w1 = (k < DD) ? W1l[j * DD + k] : W1r[j * DD + k - DD];
    float w2 = (k < DD) ? W2l[j * DD + k] : W2r[j * DD + k - DD];
    __nv_bfloat16 h, l;
    split1(w1, h, l); g_B1hi[id] = h; g_B1lo[id] = l;
    split1(w2, h, l); g_B2hi[id] = h; g_B2lo[id] = l;
}

// ---------------- mean aggregation: one warp per node; writes bf16 hi/lo ----------------
template <int LAYER>
__global__ void __launch_bounds__(256) k_agg(const float* __restrict__ x) {
    const float* feat = (LAYER == 1) ? x : (const float*)g_h1;
    int warp = (blockIdx.x * blockDim.x + threadIdx.x) >> 5;
    int lane = threadIdx.x & 31;
    if (warp >= NN) return;
    int beg = g_off[warp];
    int d   = g_deg[warp];
    float4 acc = make_float4(0.f, 0.f, 0.f, 0.f);
    for (int b = 0; b < d; b += 32) {
        int m  = min(32, d - b);
        int sl = (lane < m) ? g_adj[beg + b + lane] : 0;
        #pragma unroll 4
        for (int j = 0; j < m; j++) {
            int s = __shfl_sync(0xffffffffu, sl, j);
            const float4 v = __ldg((const float4*)(feat + (size_t)s * DD + lane * 4));
            acc.x += v.x; acc.y += v.y; acc.z += v.z; acc.w += v.w;
        }
    }
    float inv = 1.0f / (float)max(d, 1);
    acc.x *= inv; acc.y *= inv; acc.z *= inv; acc.w *= inv;
    __nv_bfloat16 h0, h1, h2, h3, l0, l1, l2, l3;
    split1(acc.x, h0, l0); split1(acc.y, h1, l1); split1(acc.z, h2, l2); split1(acc.w, h3, l3);
    size_t rb = (size_t)warp * DD;
    ((uint2*)(g_mhi + rb))[lane] = make_uint2(pk2(h0, h1), pk2(h2, h3));
    ((uint2*)(g_mlo + rb))[lane] = make_uint2(pk2(l0, l1), pk2(l2, l3));
}

// ================= tcgen05 GEMM =================
// Per CTA: 128 rows, N=128, K=256. SS bf16 MMA, fp32 TMEM accum.
// D = Ahi*Bhi + Alo*Bhi + Ahi*Blo   (2-way bf16 split emulation of fp32)
// smem: [1KB align slack] A_hi 64KB | A_lo 64KB | B 64KB (Bhi then Blo) = 193KB dynamic.

#define SM_AHI 0
#define SM_ALO 65536
#define SM_B   131072
#define DSMEM  (196608 + 1024)

static constexpr uint32_t IDESC_BF16 =
    (1u << 4) | (1u << 7) | (1u << 10) | ((128u / 8) << 17) | ((128u / 16) << 24);

// blocked SW128 atom layout: atom = 8 rows x 64 bf16 (1024B); 16 atom-rows, 4 atom-cols
__device__ __forceinline__ int sw_chunk(int row, int col) {   // col multiple of 8
    int byte = ((row >> 3) + (col >> 6) * 16) * 1024 + (row & 7) * 128 + (col & 63) * 2;
    return byte ^ ((byte >> 3) & 0x70);
}
__device__ __forceinline__ uint64_t mk_desc(uint32_t addr) {
    const uint64_t base = (2ull << 61) | (1ull << 46) | (64ull << 32) | (1ull << 16);
    return base | ((uint64_t)(addr >> 4) & 0x3FFF);
}
__device__ __forceinline__ uint64_t koff(int t) {   // K16-step t=0..15
    return (uint64_t)(((t >> 2) * 1024) + (t & 3) * 2);
}

#if TC5
__device__ __forceinline__ void mma_bf16_ss(uint32_t d, uint64_t ad, uint64_t bd,
                                            uint32_t en) {
    asm volatile(
        "{\n\t.reg .pred p;\n\tsetp.ne.u32 p, %4, 0;\n\t"
        "tcgen05.mma.cta_group::1.kind::f16 [%0], %1, %2, %3, {%5, %5, %5, %5}, p;\n\t}"
        :: "r"(d), "l"(ad), "l"(bd), "r"(IDESC_BF16), "r"(en), "r"(0u) : "memory");
}
#endif
__device__ __forceinline__ void mbar_wait(uint32_t mbar, uint32_t parity) {
    uint32_t done;
    asm volatile(
        "{\n\t.reg .pred p;\n\t"
        "mbarrier.try_wait.parity.acquire.cta.shared::cta.b64 p, [%1], %2;\n\t"
        "selp.b32 %0, 1, 0, p;\n\t}"
        : "=r"(done) : "r"(mbar), "r"(parity) : "memory");
    if (!done) {
        asm volatile(
            "{\n\t.reg .pred P1;\n\t"
            "WL_%=:\n\t"
            "mbarrier.try_wait.parity.acquire.cta.shared::cta.b64 P1, [%0], %1, 0x989680;\n\t"
            "@P1 bra.uni WD_%=;\n\t"
            "bra.uni WL_%=;\n\t"
            "WD_%=:\n\t}"
            :: "r"(mbar), "r"(parity) : "memory");
    }
}

template <int LAYER>
__global__ void __launch_bounds__(128) k_mma(
    const float* __restrict__ bias, const float* __restrict__ lnw,
    const float* __restrict__ lnb, float* __restrict__ outp)
{
#if TC5
    extern __shared__ char dsm_raw[];
    __shared__ uint32_t s_tmem;
    __shared__ __align__(8) unsigned long long s_mbar;
    __shared__ float sb[DD], slw[DD], slb[DD];

    // SW128 swizzle is defined on absolute smem address bits -> tile base MUST be
    // 1024B-aligned. extern shared is only 16B-aligned; round up (1KB slack reserved).
    const uint32_t raw_u = s2u32(dsm_raw);
    const uint32_t dsm_u = (raw_u + 1023u) & ~1023u;
    char* dsm = dsm_raw + (dsm_u - raw_u);

    const int tid  = threadIdx.x;
    const int wid  = tid >> 5;
    const int lane = tid & 31;
    const int row0 = blockIdx.x * 128;

    const __nv_bfloat16* Amh = g_mhi;
    const __nv_bfloat16* Aml = g_mlo;
    const __nv_bfloat16* Ahh = (LAYER == 1) ? g_xhi : g_h1hi;
    const __nv_bfloat16* Ahl = (LAYER == 1) ? g_xlo : g_h1lo;
    const __nv_bfloat16* Bhi = (LAYER == 1) ? g_B1hi : g_B2hi;
    const __nv_bfloat16* Blo = (LAYER == 1) ? g_B1lo : g_B2lo;

    uint32_t mbar_a = s2u32(&s_mbar);
    uint32_t tmslot = s2u32(&s_tmem);

    if (wid == 0) {
        asm volatile(
            "tcgen05.alloc.cta_group::1.sync.aligned.shared::cta.b32 [%0], %1;"
            :: "r"(tmslot), "r"(128u) : "memory");
    }
    if (tid == 0) {
        asm volatile("mbarrier.init.shared.b64 [%0], %1;" :: "r"(mbar_a), "r"(1u) : "memory");
    }
    sb[tid] = bias[tid];
    if (LAYER == 2) { slw[tid] = lnw[tid]; slb[tid] = lnb[tid]; }
    __syncthreads();
    uint32_t tmem;
    asm volatile("ld.shared.b32 %0, [%1];" : "=r"(tmem) : "r"(tmslot));

    // ---- load A hi/lo (resident) and B = Bhi ----
    {
        const uint4 zed = make_uint4(0, 0, 0, 0);
        #pragma unroll 4
        for (int c = tid; c < 4096; c += 128) {       // 16B chunks: 128 rows x 32 chunks
            int r = c >> 5, col = (c & 31) * 8;
            int gr = row0 + r;
            uint4 vh = zed, vl = zed;
            if (gr < NN) {
                size_t rb = (size_t)gr * DD;
                if (col < DD) {
                    vh = *(const uint4*)(Amh + rb + col);
                    vl = *(const uint4*)(Aml + rb + col);
                } else {
                    vh = *(const uint4*)(Ahh + rb + col - DD);
                    vl = *(const uint4*)(Ahl + rb + col - DD);
                }
            }
            int so = sw_chunk(r, col);
            *(uint4*)(dsm + SM_AHI + so) = vh;
            *(uint4*)(dsm + SM_ALO + so) = vl;
        }
        #pragma unroll 4
        for (int c = tid; c < 4096; c += 128) {       // B: 128 j-rows x 256 k
            int j = c >> 5, col = (c & 31) * 8;
            uint4 v = *(const uint4*)(Bhi + j * 256 + col);
            *(uint4*)(dsm + SM_B + sw_chunk(j, col)) = v;
        }
    }
    __syncthreads();

    uint64_t dAhi = mk_desc(dsm_u + SM_AHI);
    uint64_t dAlo = mk_desc(dsm_u + SM_ALO);
    uint64_t dB   = mk_desc(dsm_u + SM_B);

    // ---- phase A: Ahi*Bhi + Alo*Bhi ----
    if (tid == 0) {
        asm volatile("fence.proxy.async.shared::cta;" ::: "memory");
        #pragma unroll
        for (int t = 0; t < 16; t++)
            mma_bf16_ss(tmem, dAhi + koff(t), dB + koff(t), t > 0);
        #pragma unroll
        for (int t = 0; t < 16; t++)
            mma_bf16_ss(tmem, dAlo + koff(t), dB + koff(t), 1);
        asm volatile(
            "tcgen05.commit.cta_group::1.mbarrier::arrive::one.shared::cluster.b64 [%0];"
            :: "r"(mbar_a) : "memory");
    }
    mbar_wait(mbar_a, 0);

    // ---- swap B -> Blo ----
    #pragma unroll 4
    for (int c = tid; c < 4096; c += 128) {
        int j = c >> 5, col = (c & 31) * 8;
        uint4 v = *(const uint4*)(Blo + j * 256 + col);
        *(uint4*)(dsm + SM_B + sw_chunk(j, col)) = v;
    }
    __syncthreads();

    // ---- phase B: Ahi*Blo ----
    if (tid == 0) {
        asm volatile("fence.proxy.async.shared::cta;" ::: "memory");
        #pragma unroll
        for (int t = 0; t < 16; t++)
            mma_bf16_ss(tmem, dAhi + koff(t), dB + koff(t), 1);
        asm volatile(
            "tcgen05.commit.cta_group::1.mbarrier::arrive::one.shared::cluster.b64 [%0];"
            :: "r"(mbar_a) : "memory");
    }
    mbar_wait(mbar_a, 1);
    asm volatile("tcgen05.fence::after_thread_sync;" ::: "memory");

    // ---- epilogue: each thread owns one output row (TMEM lane) ----
    uint32_t dr[128];
    #define LD32(p, a) \
        asm volatile("tcgen05.ld.sync.aligned.32x32b.x32.b32 " \
            "{%0,%1,%2,%3,%4,%5,%6,%7,%8,%9,%10,%11,%12,%13,%14,%15," \
            "%16,%17,%18,%19,%20,%21,%22,%23,%24,%25,%26,%27,%28,%29,%30,%31}, [%32];" \
            : "=r"((p)[0]),"=r"((p)[1]),"=r"((p)[2]),"=r"((p)[3]),"=r"((p)[4]),"=r"((p)[5]), \
              "=r"((p)[6]),"=r"((p)[7]),"=r"((p)[8]),"=r"((p)[9]),"=r"((p)[10]),"=r"((p)[11]), \
              "=r"((p)[12]),"=r"((p)[13]),"=r"((p)[14]),"=r"((p)[15]),"=r"((p)[16]),"=r"((p)[17]), \
              "=r"((p)[18]),"=r"((p)[19]),"=r"((p)[20]),"=r"((p)[21]),"=r"((p)[22]),"=r"((p)[23]), \
              "=r"((p)[24]),"=r"((p)[25]),"=r"((p)[26]),"=r"((p)[27]),"=r"((p)[28]),"=r"((p)[29]), \
              "=r"((p)[30]),"=r"((p)[31]) : "r"(a))
    LD32(dr,      tmem);
    LD32(dr + 32, tmem + 32);
    LD32(dr + 64, tmem + 64);
    LD32(dr + 96, tmem + 96);
    asm volatile("tcgen05.wait::ld.sync.aligned;" ::: "memory");
    #undef LD32

    int gr = row0 + wid * 32 + lane;
    if (gr < NN) {
        size_t rb = (size_t)gr * DD;
        if (LAYER == 1) {
            #pragma unroll
            for (int c = 0; c < 32; c++) {
                int j = 4 * c;
                float f0 = fmaxf(__uint_as_float(dr[j])     + sb[j],     0.f);
                float f1 = fmaxf(__uint_as_float(dr[j + 1]) + sb[j + 1], 0.f);
                float f2 = fmaxf(__uint_as_float(dr[j + 2]) + sb[j + 2], 0.f);
                float f3 = fmaxf(__uint_as_float(dr[j + 3]) + sb[j + 3], 0.f);
                *(float4*)(g_h1 + rb + j) = make_float4(f0, f1, f2, f3);
                __nv_bfloat16 h0, h1, h2, h3, l0, l1, l2, l3;
                split1(f0, h0, l0); split1(f1, h1, l1);
                split1(f2, h2, l2); split1(f3, h3, l3);
                ((uint2*)(g_h1hi + rb))[c] = make_uint2(pk2(h0, h1), pk2(h2, h3));
                ((uint2*)(g_h1lo + rb))[c] = make_uint2(pk2(l0, l1), pk2(l2, l3));
            }
        } else {
            float s = 0.f, sq = 0.f;
            #pragma unroll
            for (int j = 0; j < 128; j++) {
                float f = fmaxf(__uint_as_float(dr[j]) + sb[j], 0.f);
                dr[j] = __float_as_uint(f);
                s += f; sq += f * f;
            }
            float mu  = s * (1.0f / DD);
            float var = sq * (1.0f / DD) - mu * mu;
            float rs  = rsqrtf(var + 1e-5f);
            #pragma unroll
            for (int c = 0; c < 32; c++) {
                int j = 4 * c;
                float4 o;
                o.x = (__uint_as_float(dr[j])     - mu) * rs * slw[j]     + slb[j];
                o.y = (__uint_as_float(dr[j + 1]) - mu) * rs * slw[j + 1] + slb[j + 1];
                o.z = (__uint_as_float(dr[j + 2]) - mu) * rs * slw[j + 2] + slb[j + 2];
                o.w = (__uint_as_float(dr[j + 3]) - mu) * rs * slw[j + 3] + slb[j + 3];
                *(float4*)(outp + rb + j) = o;
            }
        }
    }

    __syncthreads();
    if (tid == 0)
        asm volatile("mbarrier.inval.shared.b64 [%0];" :: "r"(mbar_a) : "memory");
    __syncthreads();
    if (wid == 0) {
        asm volatile("tcgen05.dealloc.cta_group::1.sync.aligned.b32 %0, %1;"
                     :: "r"(tmem), "r"(128u));
        asm volatile("tcgen05.relinquish_alloc_permit.cta_group::1.sync.aligned;");
    }
#endif  // TC5
}

// ---------------- launch ----------------
extern "C" void kernel_launch(void* const* d_in, const int* in_sizes, int n_in,
                              void* d_out, int out_size) {
    const float* x   = (const float*)d_in[0];
    const void*  ei  = d_in[1];
    const float* W1l = (const float*)d_in[2];
    const float* b1l = (const float*)d_in[3];
    const float* W1r = (const float*)d_in[4];
    const float* W2l = (const float*)d_in[5];
    const float* b2l = (const float*)d_in[6];
    const float* W2r = (const float*)d_in[7];
    const float* lnw = (const float*)d_in[8];
    const float* lnb = (const float*)d_in[9];
    float* out = (float*)d_out;

    cudaFuncSetAttribute(k_mma<1>, cudaFuncAttributeMaxDynamicSharedMemorySize, DSMEM);
    cudaFuncSetAttribute(k_mma<2>, cudaFuncAttributeMaxDynamicSharedMemorySize, DSMEM);

    const int scan_blocks = (NN + 2047) / 2048;  // 25
    const int mma_blocks  = (NN + 127) / 128;    // 391

    k_detect<<<1, 32>>>((const unsigned long long*)ei);
    k_zero<<<(NN + 255) / 256, 256>>>();
    k_hist<<<(NE + 255) / 256, 256>>>(ei);
    k_scan1<<<scan_blocks, 1024>>>();
    k_scan2<<<1, 32>>>(scan_blocks);
    k_scan3<<<(NN + 255) / 256, 256>>>();
    k_scatter<<<(NE + 255) / 256, 256>>>(ei);
    k_wprep<<<(DD * 2 * DD + 255) / 256, 256>>>(W1l, W1r, W2l, W2r);
    k_convx<<<(NN * (DD / 4) + 255) / 256, 256>>>(x);

    // layer 1
    k_agg<1><<<(NN * 32 + 255) / 256, 256>>>(x);
    k_mma<1><<<mma_blocks, 128, DSMEM>>>(b1l, nullptr, nullptr, out);

    // layer 2 (+ LayerNorm)
    k_agg<2><<<(NN * 32 + 255) / 256, 256>>>(x);
    k_mma<2><<<mma_blocks, 128, DSMEM>>>(b2l, lnw, lnb, out);
}

// round 7
// speedup vs baseline: 1.6145x; 1.5878x over previous
#include <cuda_runtime.h>
#include <cuda_bf16.h>
#include <cstdint>

#define NN 50000
#define NE 800000
#define DD 128

// tcgen05 is only legal on arch-specific targets (sm_103a / sm_100a).
// The harness also compiles a plain compute_103 pass -> give it a stub body.
#if !defined(__CUDA_ARCH__) || defined(__CUDA_ARCH_FEAT_SM103_ALL) || \
    defined(__CUDA_ARCH_FEAT_SM100_ALL) || defined(__CUDA_ARCH_SPECIFIC__)
#define TC5 1
#else
#define TC5 0
#endif

// ---------------- scratch (no allocs -> device globals) ----------------
__device__ int   g_deg[NN];
__device__ int   g_off[NN];      // intra-block exclusive; final = g_off[i]+g_bsum[i>>11]
__device__ int   g_cnt2[NN];
__device__ int   g_adj[NE];
__device__ int   g_bsum[32];
__device__ int   g_ticket;
__device__ int   g_is32;
__device__ __align__(16) __nv_bfloat16  g_xhi[(size_t)NN * DD];
__device__ __align__(16) __nv_bfloat16  g_xlo[(size_t)NN * DD];
__device__ __align__(16) __nv_bfloat16  g_mhi[(size_t)NN * DD];
__device__ __align__(16) __nv_bfloat16  g_mlo[(size_t)NN * DD];
__device__ __align__(16) __nv_bfloat16  g_h1hi[(size_t)NN * DD];
__device__ __align__(16) __nv_bfloat16  g_h1lo[(size_t)NN * DD];
__device__ __align__(16) __nv_bfloat16  g_B1hi[DD * 2 * DD];  // [j][k] k-major, K=256
__device__ __align__(16) __nv_bfloat16  g_B1lo[DD * 2 * DD];
__device__ __align__(16) __nv_bfloat16  g_B2hi[DD * 2 * DD];
__device__ __align__(16) __nv_bfloat16  g_B2lo[DD * 2 * DD];

// ---------------- small helpers ----------------
__device__ __forceinline__ uint32_t s2u32(const void* p) {
    uint32_t a;
    asm("{ .reg .u64 t; cvta.to.shared.u64 t, %1; cvt.u32.u64 %0, t; }" : "=r"(a) : "l"(p));
    return a;
}
__device__ __forceinline__ unsigned pk2(__nv_bfloat16 a, __nv_bfloat16 b) {
    unsigned short ua = *(unsigned short*)&a, ub = *(unsigned short*)&b;
    return (unsigned)ua | ((unsigned)ub << 16);
}
__device__ __forceinline__ void split1(float v, __nv_bfloat16& h, __nv_bfloat16& l) {
    h = __float2bfloat16_rn(v);
    l = __float2bfloat16_rn(v - __bfloat162float(h));
}
// acc += unpack2(hi) + unpack2(lo)  (pairwise)
__device__ __forceinline__ void addpair(float& a0, float& a1, unsigned h, unsigned l) {
    float2 fh = __bfloat1622float2(*(__nv_bfloat162*)&h);
    float2 fl = __bfloat1622float2(*(__nv_bfloat162*)&l);
    a0 += fh.x + fl.x;
    a1 += fh.y + fl.y;
}

__device__ __forceinline__ int load_src(const void* ei, int e) {
    return g_is32 ? ((const int*)ei)[e] : (int)((const long long*)ei)[e];
}
__device__ __forceinline__ int load_dst(const void* ei, int e) {
    return g_is32 ? ((const int*)ei)[NE + e] : (int)((const long long*)ei)[NE + e];
}

// ---------------- init: zero deg/cnt2/ticket + edge dtype detect ----------------
__global__ void k_init(const unsigned long long* __restrict__ ei) {
    int i = blockIdx.x * blockDim.x + threadIdx.x;
    if (i < NN) { g_deg[i] = 0; g_cnt2[i] = 0; }
    if (i == 0) {
        g_ticket = 0;
        int bad = 0;
        #pragma unroll
        for (int k = 0; k < 16; k++)
            if (ei[k] >= (unsigned long long)NN) bad = 1;
        g_is32 = bad;
    }
}

__global__ void k_hist(const void* __restrict__ ei) {
    int e = blockIdx.x * blockDim.x + threadIdx.x;
    if (e < NE) {
        int dst = load_dst(ei, e);
        if ((unsigned)dst < (unsigned)NN) atomicAdd(&g_deg[dst], 1);
    }
}

// scan within 2048-blocks + last-block scans the 25 block sums
__global__ void k_scan12() {
    __shared__ int sc[1024];
    __shared__ int lastFlag;
    int t = threadIdx.x;
    int base = blockIdx.x * 2048;
    int i0 = base + 2 * t, i1 = i0 + 1;
    int a = (i0 < NN) ? g_deg[i0] : 0;
    int b = (i1 < NN) ? g_deg[i1] : 0;
    sc[t] = a + b;
    __syncthreads();
    #pragma unroll
    for (int off = 1; off < 1024; off <<= 1) {
        int v = (t >= off) ? sc[t - off] : 0;
        __syncthreads();
        sc[t] += v;
        __syncthreads();
    }
    int excl = sc[t] - (a + b);
    if (i0 < NN) g_off[i0] = excl;
    if (i1 < NN) g_off[i1] = excl + a;
    if (t == 1023) g_bsum[blockIdx.x] = sc[t];
    __threadfence();
    if (t == 0) lastFlag = (atomicAdd(&g_ticket, 1) == (int)gridDim.x - 1);
    __syncthreads();
    if (lastFlag && t == 0) {
        volatile int* bs = g_bsum;
        int s = 0;
        for (int i = 0; i < (int)gridDim.x; i++) { int v = bs[i]; bs[i] = s; s += v; }
    }
}

__global__ void k_scatter(const void* __restrict__ ei) {
    int e = blockIdx.x * blockDim.x + threadIdx.x;
    if (e < NE) {
        int dst = load_dst(ei, e);
        int src = load_src(ei, e);
        if ((unsigned)dst < (unsigned)NN && (unsigned)src < (unsigned)NN) {
            int base = g_off[dst] + g_bsum[dst >> 11];
            int pos = base + atomicAdd(&g_cnt2[dst], 1);
            if ((unsigned)pos < (unsigned)NE) g_adj[pos] = src;
        }
    }
}

// ---------------- prep: weights split (blocks 0..127) + x split (rest) ----------------
#define WPREP_BLOCKS 128
__global__ void k_prep(const float* __restrict__ x,
                       const float* __restrict__ W1l, const float* __restrict__ W1r,
                       const float* __restrict__ W2l, const float* __restrict__ W2r) {
    if (blockIdx.x < WPREP_BLOCKS) {
        int id = blockIdx.x * 256 + threadIdx.x;  // < 32768
        int j = id >> 8, k = id & 255;
        float w1 = (k < DD) ? W1l[j * DD + k] : W1r[j * DD + k - DD];
        float w2 = (k < DD) ? W2l[j * DD + k] : W2r[j * DD + k - DD];
        __nv_bfloat16 h, l;
        split1(w1, h, l); g_B1hi[id] = h; g_B1lo[id] = l;
        split1(w2, h, l); g_B2hi[id] = h; g_B2lo[id] = l;
    } else {
        int i = (blockIdx.x - WPREP_BLOCKS) * 256 + threadIdx.x;  // float4 idx
        if (i >= NN * (DD / 4)) return;
        float4 v = ((const float4*)x)[i];
        __nv_bfloat16 h0, h1, h2, h3, l0, l1, l2, l3;
        split1(v.x, h0, l0); split1(v.y, h1, l1);
        split1(v.z, h2, l2); split1(v.w, h3, l3);
        ((uint2*)g_xhi)[i] = make_uint2(pk2(h0, h1), pk2(h2, h3));
        ((uint2*)g_xlo)[i] = make_uint2(pk2(l0, l1), pk2(l2, l3));
    }
}

// ---------------- mean aggregation: one warp per node; writes bf16 hi/lo ----------------
template <int LAYER>
__global__ void __launch_bounds__(256) k_agg(const float* __restrict__ x) {
    int warp = (blockIdx.x * blockDim.x + threadIdx.x) >> 5;
    int lane = threadIdx.x & 31;
    if (warp >= NN) return;
    int beg = g_off[warp] + g_bsum[warp >> 11];
    int d   = g_deg[warp];
    float4 acc = make_float4(0.f, 0.f, 0.f, 0.f);
    for (int b = 0; b < d; b += 32) {
        int m  = min(32, d - b);
        int sl = (lane < m) ? g_adj[beg + b + lane] : 0;
        #pragma unroll 4
        for (int j = 0; j < m; j++) {
            int s = __shfl_sync(0xffffffffu, sl, j);
            if (LAYER == 1) {
                const float4 v = __ldg((const float4*)(x + (size_t)s * DD) + lane);
                acc.x += v.x; acc.y += v.y; acc.z += v.z; acc.w += v.w;
            } else {
                const uint2 vh = __ldg((const uint2*)(g_h1hi + (size_t)s * DD) + lane);
                const uint2 vl = __ldg((const uint2*)(g_h1lo + (size_t)s * DD) + lane);
                addpair(acc.x, acc.y, vh.x, vl.x);
                addpair(acc.z, acc.w, vh.y, vl.y);
            }
        }
    }
    float inv = 1.0f / (float)max(d, 1);
    acc.x *= inv; acc.y *= inv; acc.z *= inv; acc.w *= inv;
    __nv_bfloat16 h0, h1, h2, h3, l0, l1, l2, l3;
    split1(acc.x, h0, l0); split1(acc.y, h1, l1);
    split1(acc.z, h2, l2); split1(acc.w, h3, l3);
    size_t rb = (size_t)warp * DD;
    ((uint2*)(g_mhi + rb))[lane] = make_uint2(pk2(h0, h1), pk2(h2, h3));
    ((uint2*)(g_mlo + rb))[lane] = make_uint2(pk2(l0, l1), pk2(l2, l3));
}

// ================= tcgen05 GEMM =================
// Per CTA: 128 rows, N=128, K=256. SS bf16 MMA, fp32 TMEM accum.
// D = Ahi*Bhi + Alo*Bhi + Ahi*Blo  (2-way bf16 split of fp32)
// smem: [1KB slack] A_hi 64KB | A_lo 64KB | B 64KB (Bhi, then Blo via reg preload).
// 256 threads. Loads via cp.async; Blo preloaded to regs under phase-A MMA shadow.

#define SM_AHI 0
#define SM_ALO 65536
#define SM_B   131072
#define DSMEM  (196608 + 1024)

static constexpr uint32_t IDESC_BF16 =
    (1u << 4) | (1u << 7) | (1u << 10) | ((128u / 8) << 17) | ((128u / 16) << 24);

// blocked SW128 atom layout: atom = 8 rows x 64 bf16 (1024B); 16 atom-rows, 4 atom-cols
__device__ __forceinline__ int sw_chunk(int row, int col) {   // col multiple of 8
    int byte = ((row >> 3) + (col >> 6) * 16) * 1024 + (row & 7) * 128 + (col & 63) * 2;
    return byte ^ ((byte >> 3) & 0x70);
}
__device__ __forceinline__ uint64_t mk_desc(uint32_t addr) {
    const uint64_t base = (2ull << 61) | (1ull << 46) | (64ull << 32) | (1ull << 16);
    return base | ((uint64_t)(addr >> 4) & 0x3FFF);
}
__device__ __forceinline__ uint64_t koff(int t) {   // K16-step t=0..15
    return (uint64_t)(((t >> 2) * 1024) + (t & 3) * 2);
}

#if TC5
__device__ __forceinline__ void mma_bf16_ss(uint32_t d, uint64_t ad, uint64_t bd,
                                            uint32_t en) {
    asm volatile(
        "{\n\t.reg .pred p;\n\tsetp.ne.u32 p, %4, 0;\n\t"
        "tcgen05.mma.cta_group::1.kind::f16 [%0], %1, %2, %3, {%5, %5, %5, %5}, p;\n\t}"
        :: "r"(d), "l"(ad), "l"(bd), "r"(IDESC_BF16), "r"(en), "r"(0u) : "memory");
}
__device__ __forceinline__ void cp16(uint32_t saddr, const void* gaddr) {
    asm volatile("cp.async.cg.shared.global [%0], [%1], 16;"
                 :: "r"(saddr), "l"(gaddr) : "memory");
}
#endif
__device__ __forceinline__ void mbar_wait(uint32_t mbar, uint32_t parity) {
    uint32_t done;
    asm volatile(
        "{\n\t.reg .pred p;\n\t"
        "mbarrier.try_wait.parity.acquire.cta.shared::cta.b64 p, [%1], %2;\n\t"
        "selp.b32 %0, 1, 0, p;\n\t}"
        : "=r"(done) : "r"(mbar), "r"(parity) : "memory");
    if (!done) {
        asm volatile(
            "{\n\t.reg .pred P1;\n\t"
            "WL_%=:\n\t"
            "mbarrier.try_wait.parity.acquire.cta.shared::cta.b64 P1, [%0], %1, 0x989680;\n\t"
            "@P1 bra.uni WD_%=;\n\t"
            "bra.uni WL_%=;\n\t"
            "WD_%=:\n\t}"
            :: "r"(mbar), "r"(parity) : "memory");
    }
}

template <int LAYER>
__global__ void __launch_bounds__(256) k_mma(
    const float* __restrict__ bias, const float* __restrict__ lnw,
    const float* __restrict__ lnb, float* __restrict__ outp)
{
#if TC5
    extern __shared__ char dsm_raw[];
    __shared__ uint32_t s_tmem;
    __shared__ __align__(8) unsigned long long s_mbar;
    __shared__ float sb[DD], slw[DD], slb[DD];
    __shared__ float psS[2][DD], psQ[2][DD];

    const uint32_t raw_u = s2u32(dsm_raw);
    const uint32_t dsm_u = (raw_u + 1023u) & ~1023u;   // SW128 needs 1KB-aligned base
    char* dsm = dsm_raw + (dsm_u - raw_u);

    const int tid  = threadIdx.x;
    const int wid  = tid >> 5;
    const int lane = tid & 31;
    const int row0 = blockIdx.x * 128;

    const __nv_bfloat16* Ahh = (LAYER == 1) ? g_xhi : g_h1hi;
    const __nv_bfloat16* Ahl = (LAYER == 1) ? g_xlo : g_h1lo;
    const __nv_bfloat16* Bhi = (LAYER == 1) ? g_B1hi : g_B2hi;
    const __nv_bfloat16* Blo = (LAYER == 1) ? g_B1lo : g_B2lo;

    uint32_t mbar_a = s2u32(&s_mbar);
    uint32_t tmslot = s2u32(&s_tmem);

    if (wid == 0) {
        asm volatile(
            "tcgen05.alloc.cta_group::1.sync.aligned.shared::cta.b32 [%0], %1;"
            :: "r"(tmslot), "r"(128u) : "memory");
    }
    if (tid == 0)
        asm volatile("mbarrier.init.shared.b64 [%0], %1;" :: "r"(mbar_a), "r"(1u) : "memory");
    if (tid < DD) {
        sb[tid] = bias[tid];
        if (LAYER == 2) { slw[tid] = lnw[tid]; slb[tid] = lnb[tid]; }
    }

    // ---- async loads: A hi/lo + B = Bhi (4096 chunks each of 16B) ----
    #pragma unroll
    for (int it = 0; it < 16; it++) {
        int c = tid + it * 256;
        int r = c >> 5, col = (c & 31) * 8;
        int gr = row0 + r; if (gr >= NN) gr = 0;   // clamp: garbage rows never stored
        size_t rb = (size_t)gr * DD;
        int so = sw_chunk(r, col);
        const __nv_bfloat16* ph = (col < DD) ? (g_mhi + rb + col) : (Ahh + rb + col - DD);
        const __nv_bfloat16* pl = (col < DD) ? (g_mlo + rb + col) : (Ahl + rb + col - DD);
        cp16(dsm_u + SM_AHI + so, ph);
        cp16(dsm_u + SM_ALO + so, pl);
        cp16(dsm_u + SM_B + so, Bhi + r * 256 + col);   // B rows: j = r (same chunk map)
    }
    asm volatile("cp.async.commit_group;" ::: "memory");
    __syncthreads();
    uint32_t tmem;
    asm volatile("ld.shared.b32 %0, [%1];" : "=r"(tmem) : "r"(tmslot));
    asm volatile("cp.async.wait_group 0;" ::: "memory");
    __syncthreads();

    uint64_t dAhi = mk_desc(dsm_u + SM_AHI);
    uint64_t dAlo = mk_desc(dsm_u + SM_ALO);
    uint64_t dB   = mk_desc(dsm_u + SM_B);

    // ---- phase A: Ahi*Bhi + Alo*Bhi ----
    if (tid == 0) {
        asm volatile("fence.proxy.async.shared::cta;" ::: "memory");
        #pragma unroll
        for (int t = 0; t < 16; t++)
            mma_bf16_ss(tmem, dAhi + koff(t), dB + koff(t), t > 0);
        #pragma unroll
        for (int t = 0; t < 16; t++)
            mma_bf16_ss(tmem, dAlo + koff(t), dB + koff(t), 1);
        asm volatile(
            "tcgen05.commit.cta_group::1.mbarrier::arrive::one.shared::cluster.b64 [%0];"
            :: "r"(mbar_a) : "memory");
    }

    // ---- preload Blo into registers under the phase-A shadow ----
    uint4 bl[16];
    #pragma unroll
    for (int it = 0; it < 16; it++) {
        int c = tid + it * 256;
        int j = c >> 5, col = (c & 31) * 8;
        bl[it] = *(const uint4*)(Blo + j * 256 + col);
    }

    mbar_wait(mbar_a, 0);

    // ---- swap B -> Blo (STS only; L2 already paid) ----
    #pragma unroll
    for (int it = 0; it < 16; it++) {
        int c = tid + it * 256;
        int j = c >> 5, col = (c & 31) * 8;
        *(uint4*)(dsm + SM_B + sw_chunk(j, col)) = bl[it];
    }
    __syncthreads();

    // ---- phase B: Ahi*Blo ----
    if (tid == 0) {
        asm volatile("fence.proxy.async.shared::cta;" ::: "memory");
        #pragma unroll
        for (int t = 0; t < 16; t++)
            mma_bf16_ss(tmem, dAhi + koff(t), dB + koff(t), 1);
        asm volatile(
            "tcgen05.commit.cta_group::1.mbarrier::arrive::one.shared::cluster.b64 [%0];"
            :: "r"(mbar_a) : "memory");
    }
    mbar_wait(mbar_a, 1);
    asm volatile("tcgen05.fence::after_thread_sync;" ::: "memory");

    // ---- epilogue: warp w -> rows (w&3)*32+lane, cols (w>>2)*64..+63 ----
    const int sub = wid & 3, half = wid >> 2;
    const int cb = half * 64;
    uint32_t dr[64];
    #define LD32(p, a) \
        asm volatile("tcgen05.ld.sync.aligned.32x32b.x32.b32 " \
            "{%0,%1,%2,%3,%4,%5,%6,%7,%8,%9,%10,%11,%12,%13,%14,%15," \
            "%16,%17,%18,%19,%20,%21,%22,%23,%24,%25,%26,%27,%28,%29,%30,%31}, [%32];" \
            : "=r"((p)[0]),"=r"((p)[1]),"=r"((p)[2]),"=r"((p)[3]),"=r"((p)[4]),"=r"((p)[5]), \
              "=r"((p)[6]),"=r"((p)[7]),"=r"((p)[8]),"=r"((p)[9]),"=r"((p)[10]),"=r"((p)[11]), \
              "=r"((p)[12]),"=r"((p)[13]),"=r"((p)[14]),"=r"((p)[15]),"=r"((p)[16]),"=r"((p)[17]), \
              "=r"((p)[18]),"=r"((p)[19]),"=r"((p)[20]),"=r"((p)[21]),"=r"((p)[22]),"=r"((p)[23]), \
              "=r"((p)[24]),"=r"((p)[25]),"=r"((p)[26]),"=r"((p)[27]),"=r"((p)[28]),"=r"((p)[29]), \
              "=r"((p)[30]),"=r"((p)[31]) : "r"(a))
    LD32(dr,      tmem + cb);
    LD32(dr + 32, tmem + cb + 32);
    asm volatile("tcgen05.wait::ld.sync.aligned;" ::: "memory");
    #undef LD32

    const int r = sub * 32 + lane;          // local row
    const int gr = row0 + r;
    float v[64];
    float s = 0.f, sq = 0.f;
    #pragma unroll
    for (int j = 0; j < 64; j++) {
        float f = fmaxf(__uint_as_float(dr[j]) + sb[cb + j], 0.f);
        v[j] = f;
        s += f; sq += f * f;
    }

    if (LAYER == 1) {
        if (gr < NN) {
            size_t rbase = (size_t)gr * DD + cb;
            #pragma unroll
            for (int c8 = 0; c8 < 8; c8++) {
                __nv_bfloat16 h[8], l[8];
                #pragma unroll
                for (int q = 0; q < 8; q++) split1(v[c8 * 8 + q], h[q], l[q]);
                uint4 uh = make_uint4(pk2(h[0],h[1]), pk2(h[2],h[3]),
                                      pk2(h[4],h[5]), pk2(h[6],h[7]));
                uint4 ul = make_uint4(pk2(l[0],l[1]), pk2(l[2],l[3]),
                                      pk2(l[4],l[5]), pk2(l[6],l[7]));
                *(uint4*)(g_h1hi + rbase + c8 * 8) = uh;
                *(uint4*)(g_h1lo + rbase + c8 * 8) = ul;
            }
        }
    } else {
        psS[half][r] = s;
        psQ[half][r] = sq;
        __syncthreads();
        float st = psS[0][r] + psS[1][r];
        float qt = psQ[0][r] + psQ[1][r];
        float mu  = st * (1.0f / DD);
        float var = qt * (1.0f / DD) - mu * mu;
        float rs  = rsqrtf(var + 1e-5f);
        if (gr < NN) {
            size_t rbase = (size_t)gr * DD + cb;
            #pragma unroll
            for (int c4 = 0; c4 < 16; c4++) {
                float4 o;
                o.x = (v[c4*4+0] - mu) * rs * slw[cb+c4*4+0] + slb[cb+c4*4+0];
                o.y = (v[c4*4+1] - mu) * rs * slw[cb+c4*4+1] + slb[cb+c4*4+1];
                o.z = (v[c4*4+2] - mu) * rs * slw[cb+c4*4+2] + slb[cb+c4*4+2];
                o.w = (v[c4*4+3] - mu) * rs * slw[cb+c4*4+3] + slb[cb+c4*4+3];
                *(float4*)(outp + rbase + c4 * 4) = o;
            }
        }
    }

    __syncthreads();
    if (tid == 0)
        asm volatile("mbarrier.inval.shared.b64 [%0];" :: "r"(mbar_a) : "memory");
    __syncthreads();
    if (wid == 0) {
        asm volatile("tcgen05.dealloc.cta_group::1.sync.aligned.b32 %0, %1;"
                     :: "r"(tmem), "r"(128u));
        asm volatile("tcgen05.relinquish_alloc_permit.cta_group::1.sync.aligned;");
    }
#endif  // TC5
}

// ---------------- launch ----------------
extern "C" void kernel_launch(void* const* d_in, const int* in_sizes, int n_in,
                              void* d_out, int out_size) {
    const float* x   = (const float*)d_in[0];
    const void*  ei  = d_in[1];
    const float* W1l = (const float*)d_in[2];
    const float* b1l = (const float*)d_in[3];
    const float* W1r = (const float*)d_in[4];
    const float* W2l = (const float*)d_in[5];
    const float* b2l = (const float*)d_in[6];
    const float* W2r = (const float*)d_in[7];
    const float* lnw = (const float*)d_in[8];
    const float* lnb = (const float*)d_in[9];
    float* out = (float*)d_out;

    cudaFuncSetAttribute(k_mma<1>, cudaFuncAttributeMaxDynamicSharedMemorySize, DSMEM);
    cudaFuncSetAttribute(k_mma<2>, cudaFuncAttributeMaxDynamicSharedMemorySize, DSMEM);

    const int scan_blocks = (NN + 2047) / 2048;                 // 25
    const int prep_blocks = WPREP_BLOCKS + (NN * (DD / 4) + 255) / 256;
    const int mma_blocks  = (NN + 127) / 128;                   // 391

    k_prep<<<prep_blocks, 256>>>(x, W1l, W1r, W2l, W2r);
    k_init<<<(NN + 255) / 256, 256>>>((const unsigned long long*)ei);
    k_hist<<<(NE + 255) / 256, 256>>>(ei);
    k_scan12<<<scan_blocks, 1024>>>();
    k_scatter<<<(NE + 255) / 256, 256>>>(ei);

    // layer 1
    k_agg<1><<<(NN * 32 + 255) / 256, 256>>>(x);
    k_mma<1><<<mma_blocks, 256, DSMEM>>>(b1l, nullptr, nullptr, out);

    // layer 2 (+ LayerNorm)
    k_agg<2><<<(NN * 32 + 255) / 256, 256>>>(x);
    k_mma<2><<<mma_blocks, 256, DSMEM>>>(b2l, lnw, lnb, out);
}

// round 8
// speedup vs baseline: 1.7317x; 1.0726x over previous
#include <cuda_runtime.h>
#include <cuda_bf16.h>
#include <cstdint>

#define NN 50000
#define NE 800000
#define DD 128
#define SCAN_BLOCKS 25

// tcgen05 is only legal on arch-specific targets (sm_103a / sm_100a).
// The harness also compiles a plain compute_103 pass -> give it a stub body.
#if !defined(__CUDA_ARCH__) || defined(__CUDA_ARCH_FEAT_SM103_ALL) || \
    defined(__CUDA_ARCH_FEAT_SM100_ALL) || defined(__CUDA_ARCH_SPECIFIC__)
#define TC5 1
#else
#define TC5 0
#endif

// ---------------- scratch (no allocs -> device globals) ----------------
__device__ int   g_deg[NN];
__device__ int   g_off[NN];      // intra-block exclusive; final = g_off[i]+pref(bsum)[i>>11]
__device__ int   g_cnt2[NN];
__device__ int   g_adj[NE];
__device__ int   g_bsum[32];     // raw per-block sums (prefix computed by consumers)
__device__ int   g_is32;
__device__ __align__(16) __nv_bfloat16  g_xhi[(size_t)NN * DD];
__device__ __align__(16) __nv_bfloat16  g_xlo[(size_t)NN * DD];
__device__ __align__(16) __nv_bfloat16  g_mhi[(size_t)NN * DD];
__device__ __align__(16) __nv_bfloat16  g_mlo[(size_t)NN * DD];
__device__ __align__(16) __nv_bfloat16  g_h1hi[(size_t)NN * DD];
__device__ __align__(16) __nv_bfloat16  g_h1lo[(size_t)NN * DD];
__device__ __align__(16) __nv_bfloat16  g_B1hi[DD * 2 * DD];  // [j][k] k-major, K=256
__device__ __align__(16) __nv_bfloat16  g_B1lo[DD * 2 * DD];
__device__ __align__(16) __nv_bfloat16  g_B2hi[DD * 2 * DD];
__device__ __align__(16) __nv_bfloat16  g_B2lo[DD * 2 * DD];

// ---------------- small helpers ----------------
__device__ __forceinline__ uint32_t s2u32(const void* p) {
    uint32_t a;
    asm("{ .reg .u64 t; cvta.to.shared.u64 t, %1; cvt.u32.u64 %0, t; }" : "=r"(a) : "l"(p));
    return a;
}
__device__ __forceinline__ unsigned pk2(__nv_bfloat16 a, __nv_bfloat16 b) {
    unsigned short ua = *(unsigned short*)&a, ub = *(unsigned short*)&b;
    return (unsigned)ua | ((unsigned)ub << 16);
}
__device__ __forceinline__ void split1(float v, __nv_bfloat16& h, __nv_bfloat16& l) {
    h = __float2bfloat16_rn(v);
    l = __float2bfloat16_rn(v - __bfloat162float(h));
}
__device__ __forceinline__ void addpair(float& a0, float& a1, unsigned h, unsigned l) {
    float2 fh = __bfloat1622float2(*(__nv_bfloat162*)&h);
    float2 fl = __bfloat1622float2(*(__nv_bfloat162*)&l);
    a0 += fh.x + fl.x;
    a1 += fh.y + fl.y;
}
__device__ __forceinline__ int load_src(const void* ei, int e) {
    return g_is32 ? ((const int*)ei)[e] : (int)((const long long*)ei)[e];
}
__device__ __forceinline__ int load_dst(const void* ei, int e) {
    return g_is32 ? ((const int*)ei)[NE + e] : (int)((const long long*)ei)[NE + e];
}

// per-block exclusive prefix of g_bsum into smem (one warp, shfl scan)
#define BSUM_PREF(spref) do {                                             \
    if (threadIdx.x < 32) {                                               \
        int gg = (threadIdx.x < SCAN_BLOCKS) ? g_bsum[threadIdx.x] : 0;   \
        int vv = gg;                                                      \
        _Pragma("unroll")                                                 \
        for (int oo = 1; oo < 32; oo <<= 1) {                             \
            int uu = __shfl_up_sync(0xffffffffu, vv, oo);                 \
            if ((int)threadIdx.x >= oo) vv += uu;                         \
        }                                                                 \
        (spref)[threadIdx.x] = vv - gg;                                   \
    }                                                                     \
    __syncthreads();                                                      \
} while (0)

// ---------------- prep: weights split + x split + deg zero + dtype detect ----------------
#define WPREP_BLOCKS 128
__global__ void k_prep(const float* __restrict__ x, const unsigned long long* __restrict__ ei,
                       const float* __restrict__ W1l, const float* __restrict__ W1r,
                       const float* __restrict__ W2l, const float* __restrict__ W2r) {
    if (blockIdx.x < WPREP_BLOCKS) {
        int id = blockIdx.x * 256 + threadIdx.x;  // < 32768
        int j = id >> 8, k = id & 255;
        float w1 = (k < DD) ? W1l[j * DD + k] : W1r[j * DD + k - DD];
        float w2 = (k < DD) ? W2l[j * DD + k] : W2r[j * DD + k - DD];
        __nv_bfloat16 h, l;
        split1(w1, h, l); g_B1hi[id] = h; g_B1lo[id] = l;
        split1(w2, h, l); g_B2hi[id] = h; g_B2lo[id] = l;
    } else {
        int i = (blockIdx.x - WPREP_BLOCKS) * 256 + threadIdx.x;  // float4 idx
        if (i < NN) { g_deg[i] = 0; g_cnt2[i] = 0; }
        if (i == 0) {
            int bad = 0;
            #pragma unroll
            for (int k = 0; k < 16; k++)
                if (ei[k] >= (unsigned long long)NN) bad = 1;
            g_is32 = bad;
        }
        if (i >= NN * (DD / 4)) return;
        float4 v = ((const float4*)x)[i];
        __nv_bfloat16 h0, h1, h2, h3, l0, l1, l2, l3;
        split1(v.x, h0, l0); split1(v.y, h1, l1);
        split1(v.z, h2, l2); split1(v.w, h3, l3);
        ((uint2*)g_xhi)[i] = make_uint2(pk2(h0, h1), pk2(h2, h3));
        ((uint2*)g_xlo)[i] = make_uint2(pk2(l0, l1), pk2(l2, l3));
    }
}

__global__ void k_hist(const void* __restrict__ ei) {
    int e = blockIdx.x * blockDim.x + threadIdx.x;
    if (e < NE) {
        int dst = load_dst(ei, e);
        if ((unsigned)dst < (unsigned)NN) atomicAdd(&g_deg[dst], 1);
    }
}

// intra-block exclusive scan; raw block totals to g_bsum (no global tail)
__global__ void k_scan1() {
    __shared__ int sc[1024];
    int t = threadIdx.x;
    int base = blockIdx.x * 2048;
    int i0 = base + 2 * t, i1 = i0 + 1;
    int a = (i0 < NN) ? g_deg[i0] : 0;
    int b = (i1 < NN) ? g_deg[i1] : 0;
    sc[t] = a + b;
    __syncthreads();
    #pragma unroll
    for (int off = 1; off < 1024; off <<= 1) {
        int v = (t >= off) ? sc[t - off] : 0;
        __syncthreads();
        sc[t] += v;
        __syncthreads();
    }
    int excl = sc[t] - (a + b);
    if (i0 < NN) g_off[i0] = excl;
    if (i1 < NN) g_off[i1] = excl + a;
    if (t == 1023) g_bsum[blockIdx.x] = sc[t];
}

__global__ void k_scatter(const void* __restrict__ ei) {
    __shared__ int spref[32];
    BSUM_PREF(spref);
    int e = blockIdx.x * blockDim.x + threadIdx.x;
    if (e < NE) {
        int dst = load_dst(ei, e);
        int src = load_src(ei, e);
        if ((unsigned)dst < (unsigned)NN && (unsigned)src < (unsigned)NN) {
            int base = g_off[dst] + spref[dst >> 11];
            int pos = base + atomicAdd(&g_cnt2[dst], 1);
            if ((unsigned)pos < (unsigned)NE) g_adj[pos] = src;
        }
    }
}

// ---------------- mean aggregation: one warp per node; writes bf16 hi/lo ----------------
template <int LAYER>
__global__ void __launch_bounds__(256) k_agg(const float* __restrict__ x) {
    __shared__ int spref[32];
    BSUM_PREF(spref);
    int warp = (blockIdx.x * blockDim.x + threadIdx.x) >> 5;
    int lane = threadIdx.x & 31;
    if (warp >= NN) return;
    int beg = g_off[warp] + spref[(warp >> 11) & 31];
    int d   = g_deg[warp];
    float4 acc = make_float4(0.f, 0.f, 0.f, 0.f);
    for (int b = 0; b < d; b += 32) {
        int m  = min(32, d - b);
        int sl = (lane < m) ? g_adj[beg + b + lane] : 0;
        #pragma unroll 4
        for (int j = 0; j < m; j++) {
            int s = __shfl_sync(0xffffffffu, sl, j);
            if (LAYER == 1) {
                const float4 v = __ldg((const float4*)(x + (size_t)s * DD) + lane);
                acc.x += v.x; acc.y += v.y; acc.z += v.z; acc.w += v.w;
            } else {
                const uint2 vh = __ldg((const uint2*)(g_h1hi + (size_t)s * DD) + lane);
                const uint2 vl = __ldg((const uint2*)(g_h1lo + (size_t)s * DD) + lane);
                addpair(acc.x, acc.y, vh.x, vl.x);
                addpair(acc.z, acc.w, vh.y, vl.y);
            }
        }
    }
    float inv = 1.0f / (float)max(d, 1);
    acc.x *= inv; acc.y *= inv; acc.z *= inv; acc.w *= inv;
    __nv_bfloat16 h0, h1, h2, h3, l0, l1, l2, l3;
    split1(acc.x, h0, l0); split1(acc.y, h1, l1);
    split1(acc.z, h2, l2); split1(acc.w, h3, l3);
    size_t rb = (size_t)warp * DD;
    ((uint2*)(g_mhi + rb))[lane] = make_uint2(pk2(h0, h1), pk2(h2, h3));
    ((uint2*)(g_mlo + rb))[lane] = make_uint2(pk2(l0, l1), pk2(l2, l3));
}

// ================= tcgen05 GEMM =================
// Per CTA: 128 rows, N=128, K=256. SS bf16 MMA, fp32 TMEM accum.
// D = Ahi*Bhi + Alo*Bhi + Ahi*Blo  (2-way bf16 split of fp32)
// smem: [1KB slack] A_hi 64KB | A_lo 64KB | B 64KB (Bhi, then Blo via reg preload).
// 256 threads. cp.async in 2 groups: {B,Ahi} then {Alo}; phase-A-hi MMAs overlap Alo load.

#define SM_AHI 0
#define SM_ALO 65536
#define SM_B   131072
#define DSMEM  (196608 + 1024)

static constexpr uint32_t IDESC_BF16 =
    (1u << 4) | (1u << 7) | (1u << 10) | ((128u / 8) << 17) | ((128u / 16) << 24);

// blocked SW128 atom layout: atom = 8 rows x 64 bf16 (1024B); 16 atom-rows, 4 atom-cols
__device__ __forceinline__ int sw_chunk(int row, int col) {   // col multiple of 8
    int byte = ((row >> 3) + (col >> 6) * 16) * 1024 + (row & 7) * 128 + (col & 63) * 2;
    return byte ^ ((byte >> 3) & 0x70);
}
__device__ __forceinline__ uint64_t mk_desc(uint32_t addr) {
    const uint64_t base = (2ull << 61) | (1ull << 46) | (64ull << 32) | (1ull << 16);
    return base | ((uint64_t)(addr >> 4) & 0x3FFF);
}
__device__ __forceinline__ uint64_t koff(int t) {   // K16-step t=0..15
    return (uint64_t)(((t >> 2) * 1024) + (t & 3) * 2);
}

#if TC5
__device__ __forceinline__ void mma_bf16_ss(uint32_t d, uint64_t ad, uint64_t bd,
                                            uint32_t en) {
    asm volatile(
        "{\n\t.reg .pred p;\n\tsetp.ne.u32 p, %4, 0;\n\t"
        "tcgen05.mma.cta_group::1.kind::f16 [%0], %1, %2, %3, {%5, %5, %5, %5}, p;\n\t}"
        :: "r"(d), "l"(ad), "l"(bd), "r"(IDESC_BF16), "r"(en), "r"(0u) : "memory");
}
__device__ __forceinline__ void cp16(uint32_t saddr, const void* gaddr) {
    asm volatile("cp.async.cg.shared.global [%0], [%1], 16;"
                 :: "r"(saddr), "l"(gaddr) : "memory");
}
#endif
__device__ __forceinline__ void mbar_wait(uint32_t mbar, uint32_t parity) {
    uint32_t done;
    asm volatile(
        "{\n\t.reg .pred p;\n\t"
        "mbarrier.try_wait.parity.acquire.cta.shared::cta.b64 p, [%1], %2;\n\t"
        "selp.b32 %0, 1, 0, p;\n\t}"
        : "=r"(done) : "r"(mbar), "r"(parity) : "memory");
    if (!done) {
        asm volatile(
            "{\n\t.reg .pred P1;\n\t"
            "WL_%=:\n\t"
            "mbarrier.try_wait.parity.acquire.cta.shared::cta.b64 P1, [%0], %1, 0x989680;\n\t"
            "@P1 bra.uni WD_%=;\n\t"
            "bra.uni WL_%=;\n\t"
            "WD_%=:\n\t}"
            :: "r"(mbar), "r"(parity) : "memory");
    }
}

template <int LAYER>
__global__ void __launch_bounds__(256) k_mma(
    const float* __restrict__ bias, const float* __restrict__ lnw,
    const float* __restrict__ lnb, float* __restrict__ outp)
{
#if TC5
    extern __shared__ char dsm_raw[];
    __shared__ uint32_t s_tmem;
    __shared__ __align__(8) unsigned long long s_mbar;
    __shared__ float sb[DD], slw[DD], slb[DD];
    __shared__ float psS[2][DD], psQ[2][DD];

    const uint32_t raw_u = s2u32(dsm_raw);
    const uint32_t dsm_u = (raw_u + 1023u) & ~1023u;   // SW128 needs 1KB-aligned base
    char* dsm = dsm_raw + (dsm_u - raw_u);

    const int tid  = threadIdx.x;
    const int wid  = tid >> 5;
    const int lane = tid & 31;
    const int row0 = blockIdx.x * 128;

    const __nv_bfloat16* Ahh = (LAYER == 1) ? g_xhi : g_h1hi;
    const __nv_bfloat16* Ahl = (LAYER == 1) ? g_xlo : g_h1lo;
    const __nv_bfloat16* Bhi = (LAYER == 1) ? g_B1hi : g_B2hi;
    const __nv_bfloat16* Blo = (LAYER == 1) ? g_B1lo : g_B2lo;

    uint32_t mbar_a = s2u32(&s_mbar);
    uint32_t tmslot = s2u32(&s_tmem);

    if (wid == 0) {
        asm volatile(
            "tcgen05.alloc.cta_group::1.sync.aligned.shared::cta.b32 [%0], %1;"
            :: "r"(tmslot), "r"(128u) : "memory");
    }
    if (tid == 0)
        asm volatile("mbarrier.init.shared.b64 [%0], %1;" :: "r"(mbar_a), "r"(1u) : "memory");
    if (tid < DD) {
        sb[tid] = bias[tid];
        if (LAYER == 2) { slw[tid] = lnw[tid]; slb[tid] = lnb[tid]; }
    }

    // ---- async loads, 2 groups: {B, Ahi} then {Alo} ----
    int rr[16], cc[16], so[16];
    #pragma unroll
    for (int it = 0; it < 16; it++) {
        int c = tid + it * 256;
        rr[it] = c >> 5; cc[it] = (c & 31) * 8;
        so[it] = sw_chunk(rr[it], cc[it]);
    }
    #pragma unroll
    for (int it = 0; it < 16; it++)
        cp16(dsm_u + SM_B + so[it], Bhi + rr[it] * 256 + cc[it]);
    #pragma unroll
    for (int it = 0; it < 16; it++) {
        int gr = row0 + rr[it]; if (gr >= NN) gr = 0;   // clamp: rows never stored
        size_t rb = (size_t)gr * DD;
        const __nv_bfloat16* ph = (cc[it] < DD) ? (g_mhi + rb + cc[it]) : (Ahh + rb + cc[it] - DD);
        cp16(dsm_u + SM_AHI + so[it], ph);
    }
    asm volatile("cp.async.commit_group;" ::: "memory");     // group: B + Ahi
    #pragma unroll
    for (int it = 0; it < 16; it++) {
        int gr = row0 + rr[it]; if (gr >= NN) gr = 0;
        size_t rb = (size_t)gr * DD;
        const __nv_bfloat16* pl = (cc[it] < DD) ? (g_mlo + rb + cc[it]) : (Ahl + rb + cc[it] - DD);
        cp16(dsm_u + SM_ALO + so[it], pl);
    }
    asm volatile("cp.async.commit_group;" ::: "memory");     // group: Alo

    __syncthreads();   // alloc + mbar init visible
    uint32_t tmem;
    asm volatile("ld.shared.b32 %0, [%1];" : "=r"(tmem) : "r"(tmslot));

    uint64_t dAhi = mk_desc(dsm_u + SM_AHI);
    uint64_t dAlo = mk_desc(dsm_u + SM_ALO);
    uint64_t dB   = mk_desc(dsm_u + SM_B);

    // ---- phase A1: Ahi*Bhi (Alo still streaming in) ----
    asm volatile("cp.async.wait_group 1;" ::: "memory");
    __syncthreads();
    if (tid == 0) {
        asm volatile("fence.proxy.async.shared::cta;" ::: "memory");
        #pragma unroll
        for (int t = 0; t < 16; t++)
            mma_bf16_ss(tmem, dAhi + koff(t), dB + koff(t), t > 0);
    }
    // ---- phase A2: Alo*Bhi ----
    asm volatile("cp.async.wait_group 0;" ::: "memory");
    __syncthreads();
    if (tid == 0) {
        asm volatile("fence.proxy.async.shared::cta;" ::: "memory");
        #pragma unroll
        for (int t = 0; t < 16; t++)
            mma_bf16_ss(tmem, dAlo + koff(t), dB + koff(t), 1);
        asm volatile(
            "tcgen05.commit.cta_group::1.mbarrier::arrive::one.shared::cluster.b64 [%0];"
            :: "r"(mbar_a) : "memory");
    }

    // ---- preload Blo into registers under the phase-A shadow ----
    uint4 bl[16];
    #pragma unroll
    for (int it = 0; it < 16; it++)
        bl[it] = *(const uint4*)(Blo + rr[it] * 256 + cc[it]);

    mbar_wait(mbar_a, 0);

    // ---- swap B -> Blo (STS only) ----
    #pragma unroll
    for (int it = 0; it < 16; it++)
        *(uint4*)(dsm + SM_B + so[it]) = bl[it];
    __syncthreads();

    // ---- phase B: Ahi*Blo ----
    if (tid == 0) {
        asm volatile("fence.proxy.async.shared::cta;" ::: "memory");
        #pragma unroll
        for (int t = 0; t < 16; t++)
            mma_bf16_ss(tmem, dAhi + koff(t), dB + koff(t), 1);
        asm volatile(
            "tcgen05.commit.cta_group::1.mbarrier::arrive::one.shared::cluster.b64 [%0];"
            :: "r"(mbar_a) : "memory");
    }
    mbar_wait(mbar_a, 1);
    asm volatile("tcgen05.fence::after_thread_sync;" ::: "memory");

    // ---- epilogue: warp w -> rows (w&3)*32+lane, cols (w>>2)*64..+63 ----
    const int sub = wid & 3, half = wid >> 2;
    const int cb = half * 64;
    uint32_t dr[64];
    #define LD32(p, a) \
        asm volatile("tcgen05.ld.sync.aligned.32x32b.x32.b32 " \
            "{%0,%1,%2,%3,%4,%5,%6,%7,%8,%9,%10,%11,%12,%13,%14,%15," \
            "%16,%17,%18,%19,%20,%21,%22,%23,%24,%25,%26,%27,%28,%29,%30,%31}, [%32];" \
            : "=r"((p)[0]),"=r"((p)[1]),"=r"((p)[2]),"=r"((p)[3]),"=r"((p)[4]),"=r"((p)[5]), \
              "=r"((p)[6]),"=r"((p)[7]),"=r"((p)[8]),"=r"((p)[9]),"=r"((p)[10]),"=r"((p)[11]), \
              "=r"((p)[12]),"=r"((p)[13]),"=r"((p)[14]),"=r"((p)[15]),"=r"((p)[16]),"=r"((p)[17]), \
              "=r"((p)[18]),"=r"((p)[19]),"=r"((p)[20]),"=r"((p)[21]),"=r"((p)[22]),"=r"((p)[23]), \
              "=r"((p)[24]),"=r"((p)[25]),"=r"((p)[26]),"=r"((p)[27]),"=r"((p)[28]),"=r"((p)[29]), \
              "=r"((p)[30]),"=r"((p)[31]) : "r"(a))
    LD32(dr,      tmem + cb);
    LD32(dr + 32, tmem + cb + 32);
    asm volatile("tcgen05.wait::ld.sync.aligned;" ::: "memory");
    #undef LD32

    const int r = sub * 32 + lane;          // local row
    const int gr = row0 + r;
    float v[64];
    float s = 0.f, sq = 0.f;
    #pragma unroll
    for (int j = 0; j < 64; j++) {
        float f = fmaxf(__uint_as_float(dr[j]) + sb[cb + j], 0.f);
        v[j] = f;
        s += f; sq += f * f;
    }

    if (LAYER == 1) {
        if (gr < NN) {
            size_t rbase = (size_t)gr * DD + cb;
            #pragma unroll
            for (int c8 = 0; c8 < 8; c8++) {
                __nv_bfloat16 h[8], l[8];
                #pragma unroll
                for (int q = 0; q < 8; q++) split1(v[c8 * 8 + q], h[q], l[q]);
                uint4 uh = make_uint4(pk2(h[0],h[1]), pk2(h[2],h[3]),
                                      pk2(h[4],h[5]), pk2(h[6],h[7]));
                uint4 ul = make_uint4(pk2(l[0],l[1]), pk2(l[2],l[3]),
                                      pk2(l[4],l[5]), pk2(l[6],l[7]));
                *(uint4*)(g_h1hi + rbase + c8 * 8) = uh;
                *(uint4*)(g_h1lo + rbase + c8 * 8) = ul;
            }
        }
    } else {
        psS[half][r] = s;
        psQ[half][r] = sq;
        __syncthreads();
        float st = psS[0][r] + psS[1][r];
        float qt = psQ[0][r] + psQ[1][r];
        float mu  = st * (1.0f / DD);
        float var = qt * (1.0f / DD) - mu * mu;
        float rs  = rsqrtf(var + 1e-5f);
        if (gr < NN) {
            size_t rbase = (size_t)gr * DD + cb;
            #pragma unroll
            for (int c4 = 0; c4 < 16; c4++) {
                float4 o;
                o.x = (v[c4*4+0] - mu) * rs * slw[cb+c4*4+0] + slb[cb+c4*4+0];
                o.y = (v[c4*4+1] - mu) * rs * slw[cb+c4*4+1] + slb[cb+c4*4+1];
                o.z = (v[c4*4+2] - mu) * rs * slw[cb+c4*4+2] + slb[cb+c4*4+2];
                o.w = (v[c4*4+3] - mu) * rs * slw[cb+c4*4+3] + slb[cb+c4*4+3];
                *(float4*)(outp + rbase + c4 * 4) = o;
            }
        }
    }

    __syncthreads();
    if (tid == 0)
        asm volatile("mbarrier.inval.shared.b64 [%0];" :: "r"(mbar_a) : "memory");
    __syncthreads();
    if (wid == 0) {
        asm volatile("tcgen05.dealloc.cta_group::1.sync.aligned.b32 %0, %1;"
                     :: "r"(tmem), "r"(128u));
        asm volatile("tcgen05.relinquish_alloc_permit.cta_group::1.sync.aligned;");
    }
#endif  // TC5
}

// ---------------- launch ----------------
extern "C" void kernel_launch(void* const* d_in, const int* in_sizes, int n_in,
                              void* d_out, int out_size) {
    const float* x   = (const float*)d_in[0];
    const void*  ei  = d_in[1];
    const float* W1l = (const float*)d_in[2];
    const float* b1l = (const float*)d_in[3];
    const float* W1r = (const float*)d_in[4];
    const float* W2l = (const float*)d_in[5];
    const float* b2l = (const float*)d_in[6];
    const float* W2r = (const float*)d_in[7];
    const float* lnw = (const float*)d_in[8];
    const float* lnb = (const float*)d_in[9];
    float* out = (float*)d_out;

    cudaFuncSetAttribute(k_mma<1>, cudaFuncAttributeMaxDynamicSharedMemorySize, DSMEM);
    cudaFuncSetAttribute(k_mma<2>, cudaFuncAttributeMaxDynamicSharedMemorySize, DSMEM);

    const int prep_blocks = WPREP_BLOCKS + (NN * (DD / 4) + 255) / 256;
    const int mma_blocks  = (NN + 127) / 128;                   // 391

    k_prep<<<prep_blocks, 256>>>(x, (const unsigned long long*)ei, W1l, W1r, W2l, W2r);
    k_hist<<<(NE + 255) / 256, 256>>>(ei);
    k_scan1<<<SCAN_BLOCKS, 1024>>>();
    k_scatter<<<(NE + 255) / 256, 256>>>(ei);

    // layer 1
    k_agg<1><<<(NN * 32 + 255) / 256, 256>>>(x);
    k_mma<1><<<mma_blocks, 256, DSMEM>>>(b1l, nullptr, nullptr, out);

    // layer 2 (+ LayerNorm)
    k_agg<2><<<(NN * 32 + 255) / 256, 256>>>(x);
    k_mma<2><<<mma_blocks, 256, DSMEM>>>(b2l, lnw, lnb, out);
}

// round 9
// speedup vs baseline: 1.7389x; 1.0041x over previous
#include <cuda_runtime.h>
#include <cuda_bf16.h>
#include <cstdint>

#define NN 50000
#define NE 800000
#define DD 128
#define SCAN_BLOCKS 25

// tcgen05 is only legal on arch-specific targets (sm_103a / sm_100a).
// The harness also compiles a plain compute_103 pass -> give it a stub body.
#if !defined(__CUDA_ARCH__) || defined(__CUDA_ARCH_FEAT_SM103_ALL) || \
    defined(__CUDA_ARCH_FEAT_SM100_ALL) || defined(__CUDA_ARCH_SPECIFIC__)
#define TC5 1
#else
#define TC5 0
#endif

// ---------------- scratch (no allocs -> device globals) ----------------
__device__ int   g_deg[NN];
__device__ int   g_off[NN];      // intra-block exclusive; final = g_off[i]+pref(bsum)[i>>11]
__device__ int   g_rank[NE];     // per-edge slot within its dst segment (from hist atomic)
__device__ int   g_adj[NE];
__device__ int   g_bsum[32];     // raw per-block sums (prefix computed by consumers)
__device__ int   g_is32;
__device__ __align__(16) __nv_bfloat16  g_xhi[(size_t)NN * DD];
__device__ __align__(16) __nv_bfloat16  g_xlo[(size_t)NN * DD];
__device__ __align__(16) __nv_bfloat16  g_mhi[(size_t)NN * DD];
__device__ __align__(16) __nv_bfloat16  g_mlo[(size_t)NN * DD];
__device__ __align__(16) __nv_bfloat16  g_h1hi[(size_t)NN * DD];
__device__ __align__(16) __nv_bfloat16  g_h1lo[(size_t)NN * DD];
__device__ __align__(16) __nv_bfloat16  g_B1hi[DD * 2 * DD];  // [j][k] k-major, K=256
__device__ __align__(16) __nv_bfloat16  g_B1lo[DD * 2 * DD];
__device__ __align__(16) __nv_bfloat16  g_B2hi[DD * 2 * DD];
__device__ __align__(16) __nv_bfloat16  g_B2lo[DD * 2 * DD];

// ---------------- small helpers ----------------
__device__ __forceinline__ uint32_t s2u32(const void* p) {
    uint32_t a;
    asm("{ .reg .u64 t; cvta.to.shared.u64 t, %1; cvt.u32.u64 %0, t; }" : "=r"(a) : "l"(p));
    return a;
}
__device__ __forceinline__ unsigned pk2(__nv_bfloat16 a, __nv_bfloat16 b) {
    unsigned short ua = *(unsigned short*)&a, ub = *(unsigned short*)&b;
    return (unsigned)ua | ((unsigned)ub << 16);
}
__device__ __forceinline__ void split1(float v, __nv_bfloat16& h, __nv_bfloat16& l) {
    h = __float2bfloat16_rn(v);
    l = __float2bfloat16_rn(v - __bfloat162float(h));
}
__device__ __forceinline__ void addpair(float& a0, float& a1, unsigned h, unsigned l) {
    float2 fh = __bfloat1622float2(*(__nv_bfloat162*)&h);
    float2 fl = __bfloat1622float2(*(__nv_bfloat162*)&l);
    a0 += fh.x + fl.x;
    a1 += fh.y + fl.y;
}
__device__ __forceinline__ int load_src(const void* ei, int e) {
    return g_is32 ? ((const int*)ei)[e] : (int)((const long long*)ei)[e];
}
__device__ __forceinline__ int load_dst(const void* ei, int e) {
    return g_is32 ? ((const int*)ei)[NE + e] : (int)((const long long*)ei)[NE + e];
}

// per-block exclusive prefix of g_bsum into smem (one warp, shfl scan)
#define BSUM_PREF(spref) do {                                             \
    if (threadIdx.x < 32) {                                               \
        int gg = (threadIdx.x < SCAN_BLOCKS) ? g_bsum[threadIdx.x] : 0;   \
        int vv = gg;                                                      \
        _Pragma("unroll")                                                 \
        for (int oo = 1; oo < 32; oo <<= 1) {                             \
            int uu = __shfl_up_sync(0xffffffffu, vv, oo);                 \
            if ((int)threadIdx.x >= oo) vv += uu;                         \
        }                                                                 \
        (spref)[threadIdx.x] = vv - gg;                                   \
    }                                                                     \
    __syncthreads();                                                      \
} while (0)

// ---------------- zero + dtype detect (must precede fused prep/hist) ----------------
__global__ void k_zero(const unsigned long long* __restrict__ ei) {
    int i = blockIdx.x * blockDim.x + threadIdx.x;
    if (i < NN) g_deg[i] = 0;
    if (i == 0) {
        int bad = 0;
        #pragma unroll
        for (int k = 0; k < 16; k++)
            if (ei[k] >= (unsigned long long)NN) bad = 1;
        g_is32 = bad;
    }
}

// ---------------- fused: weight split | x split | hist(+rank) as block ranges ----------------
#define WPREP_BLOCKS 128
#define XS_BLOCKS    ((NN * (DD / 4) + 255) / 256)     // 6250
#define HIST_BLOCKS  ((NE + 255) / 256)                // 3125
__global__ void k_ph(const float* __restrict__ x, const void* __restrict__ ei,
                     const float* __restrict__ W1l, const float* __restrict__ W1r,
                     const float* __restrict__ W2l, const float* __restrict__ W2r) {
    int b = blockIdx.x;
    if (b < WPREP_BLOCKS) {
        int id = b * 256 + threadIdx.x;  // < 32768
        int j = id >> 8, k = id & 255;
        float w1 = (k < DD) ? W1l[j * DD + k] : W1r[j * DD + k - DD];
        float w2 = (k < DD) ? W2l[j * DD + k] : W2r[j * DD + k - DD];
        __nv_bfloat16 h, l;
        split1(w1, h, l); g_B1hi[id] = h; g_B1lo[id] = l;
        split1(w2, h, l); g_B2hi[id] = h; g_B2lo[id] = l;
    } else if (b < WPREP_BLOCKS + XS_BLOCKS) {
        int i = (b - WPREP_BLOCKS) * 256 + threadIdx.x;  // float4 idx
        if (i >= NN * (DD / 4)) return;
        float4 v = ((const float4*)x)[i];
        __nv_bfloat16 h0, h1, h2, h3, l0, l1, l2, l3;
        split1(v.x, h0, l0); split1(v.y, h1, l1);
        split1(v.z, h2, l2); split1(v.w, h3, l3);
        ((uint2*)g_xhi)[i] = make_uint2(pk2(h0, h1), pk2(h2, h3));
        ((uint2*)g_xlo)[i] = make_uint2(pk2(l0, l1), pk2(l2, l3));
    } else {
        int e = (b - WPREP_BLOCKS - XS_BLOCKS) * 256 + threadIdx.x;
        if (e < NE) {
            int dst = load_dst(ei, e);
            if ((unsigned)dst < (unsigned)NN)
                g_rank[e] = atomicAdd(&g_deg[dst], 1);
        }
    }
}

// intra-block exclusive scan; raw block totals to g_bsum (no global tail)
__global__ void k_scan1() {
    __shared__ int sc[1024];
    int t = threadIdx.x;
    int base = blockIdx.x * 2048;
    int i0 = base + 2 * t, i1 = i0 + 1;
    int a = (i0 < NN) ? g_deg[i0] : 0;
    int b = (i1 < NN) ? g_deg[i1] : 0;
    sc[t] = a + b;
    __syncthreads();
    #pragma unroll
    for (int off = 1; off < 1024; off <<= 1) {
        int v = (t >= off) ? sc[t - off] : 0;
        __syncthreads();
        sc[t] += v;
        __syncthreads();
    }
    int excl = sc[t] - (a + b);
    if (i0 < NN) g_off[i0] = excl;
    if (i1 < NN) g_off[i1] = excl + a;
    if (t == 1023) g_bsum[blockIdx.x] = sc[t];
}

// scatter: no atomics (rank precomputed in hist)
__global__ void k_scatter(const void* __restrict__ ei) {
    __shared__ int spref[32];
    BSUM_PREF(spref);
    int e = blockIdx.x * blockDim.x + threadIdx.x;
    if (e < NE) {
        int dst = load_dst(ei, e);
        int src = load_src(ei, e);
        if ((unsigned)dst < (unsigned)NN && (unsigned)src < (unsigned)NN) {
            int pos = g_off[dst] + spref[dst >> 11] + g_rank[e];
            if ((unsigned)pos < (unsigned)NE) g_adj[pos] = src;
        }
    }
}

// ---------------- mean aggregation: one warp per node; writes bf16 hi/lo ----------------
template <int LAYER>
__global__ void __launch_bounds__(256) k_agg(const float* __restrict__ x) {
    __shared__ int spref[32];
    BSUM_PREF(spref);
    int warp = (blockIdx.x * blockDim.x + threadIdx.x) >> 5;
    int lane = threadIdx.x & 31;
    if (warp >= NN) return;
    int beg = g_off[warp] + spref[(warp >> 11) & 31];
    int d   = g_deg[warp];
    float4 acc = make_float4(0.f, 0.f, 0.f, 0.f);
    for (int b = 0; b < d; b += 32) {
        int m  = min(32, d - b);
        int sl = (lane < m) ? g_adj[beg + b + lane] : 0;
        #pragma unroll 4
        for (int j = 0; j < m; j++) {
            int s = __shfl_sync(0xffffffffu, sl, j);
            if (LAYER == 1) {
                const float4 v = __ldg((const float4*)(x + (size_t)s * DD) + lane);
                acc.x += v.x; acc.y += v.y; acc.z += v.z; acc.w += v.w;
            } else {
                const uint2 vh = __ldg((const uint2*)(g_h1hi + (size_t)s * DD) + lane);
                const uint2 vl = __ldg((const uint2*)(g_h1lo + (size_t)s * DD) + lane);
                addpair(acc.x, acc.y, vh.x, vl.x);
                addpair(acc.z, acc.w, vh.y, vl.y);
            }
        }
    }
    float inv = 1.0f / (float)max(d, 1);
    acc.x *= inv; acc.y *= inv; acc.z *= inv; acc.w *= inv;
    __nv_bfloat16 h0, h1, h2, h3, l0, l1, l2, l3;
    split1(acc.x, h0, l0); split1(acc.y, h1, l1);
    split1(acc.z, h2, l2); split1(acc.w, h3, l3);
    size_t rb = (size_t)warp * DD;
    ((uint2*)(g_mhi + rb))[lane] = make_uint2(pk2(h0, h1), pk2(h2, h3));
    ((uint2*)(g_mlo + rb))[lane] = make_uint2(pk2(l0, l1), pk2(l2, l3));
}

// ================= tcgen05 GEMM =================
// Per CTA: 128 rows, N=128, K=256. SS bf16 MMA, fp32 TMEM accum.
// D = Ahi*Bhi + Alo*Bhi + Ahi*Blo  (2-way bf16 split of fp32)
// smem: [1KB slack] A_hi 64KB | A_lo 64KB | B 64KB (Bhi, then Blo via reg preload).
// 256 threads. cp.async in 2 groups: {B,Ahi} then {Alo}; phase-A-hi MMAs overlap Alo load.

#define SM_AHI 0
#define SM_ALO 65536
#define SM_B   131072
#define DSMEM  (196608 + 1024)

static constexpr uint32_t IDESC_BF16 =
    (1u << 4) | (1u << 7) | (1u << 10) | ((128u / 8) << 17) | ((128u / 16) << 24);

// blocked SW128 atom layout: atom = 8 rows x 64 bf16 (1024B); 16 atom-rows, 4 atom-cols
__device__ __forceinline__ int sw_chunk(int row, int col) {   // col multiple of 8
    int byte = ((row >> 3) + (col >> 6) * 16) * 1024 + (row & 7) * 128 + (col & 63) * 2;
    return byte ^ ((byte >> 3) & 0x70);
}
__device__ __forceinline__ uint64_t mk_desc(uint32_t addr) {
    const uint64_t base = (2ull << 61) | (1ull << 46) | (64ull << 32) | (1ull << 16);
    return base | ((uint64_t)(addr >> 4) & 0x3FFF);
}
__device__ __forceinline__ uint64_t koff(int t) {   // K16-step t=0..15
    return (uint64_t)(((t >> 2) * 1024) + (t & 3) * 2);
}

#if TC5
__device__ __forceinline__ void mma_bf16_ss(uint32_t d, uint64_t ad, uint64_t bd,
                                            uint32_t en) {
    asm volatile(
        "{\n\t.reg .pred p;\n\tsetp.ne.u32 p, %4, 0;\n\t"
        "tcgen05.mma.cta_group::1.kind::f16 [%0], %1, %2, %3, {%5, %5, %5, %5}, p;\n\t}"
        :: "r"(d), "l"(ad), "l"(bd), "r"(IDESC_BF16), "r"(en), "r"(0u) : "memory");
}
__device__ __forceinline__ void cp16(uint32_t saddr, const void* gaddr) {
    asm volatile("cp.async.cg.shared.global [%0], [%1], 16;"
                 :: "r"(saddr), "l"(gaddr) : "memory");
}
#endif
__device__ __forceinline__ void mbar_wait(uint32_t mbar, uint32_t parity) {
    uint32_t done;
    asm volatile(
        "{\n\t.reg .pred p;\n\t"
        "mbarrier.try_wait.parity.acquire.cta.shared::cta.b64 p, [%1], %2;\n\t"
        "selp.b32 %0, 1, 0, p;\n\t}"
        : "=r"(done) : "r"(mbar), "r"(parity) : "memory");
    if (!done) {
        asm volatile(
            "{\n\t.reg .pred P1;\n\t"
            "WL_%=:\n\t"
            "mbarrier.try_wait.parity.acquire.cta.shared::cta.b64 P1, [%0], %1, 0x989680;\n\t"
            "@P1 bra.uni WD_%=;\n\t"
            "bra.uni WL_%=;\n\t"
            "WD_%=:\n\t}"
            :: "r"(mbar), "r"(parity) : "memory");
    }
}

template <int LAYER>
__global__ void __launch_bounds__(256) k_mma(
    const float* __restrict__ bias, const float* __restrict__ lnw,
    const float* __restrict__ lnb, float* __restrict__ outp)
{
#if TC5
    extern __shared__ char dsm_raw[];
    __shared__ uint32_t s_tmem;
    __shared__ __align__(8) unsigned long long s_mbar;
    __shared__ float sb[DD], slw[DD], slb[DD];
    __shared__ float psS[2][DD], psQ[2][DD];

    const uint32_t raw_u = s2u32(dsm_raw);
    const uint32_t dsm_u = (raw_u + 1023u) & ~1023u;   // SW128 needs 1KB-aligned base
    char* dsm = dsm_raw + (dsm_u - raw_u);

    const int tid  = threadIdx.x;
    const int wid  = tid >> 5;
    const int lane = tid & 31;
    const int row0 = blockIdx.x * 128;

    const __nv_bfloat16* Ahh = (LAYER == 1) ? g_xhi : g_h1hi;
    const __nv_bfloat16* Ahl = (LAYER == 1) ? g_xlo : g_h1lo;
    const __nv_bfloat16* Bhi = (LAYER == 1) ? g_B1hi : g_B2hi;
    const __nv_bfloat16* Blo = (LAYER == 1) ? g_B1lo : g_B2lo;

    uint32_t mbar_a = s2u32(&s_mbar);
    uint32_t tmslot = s2u32(&s_tmem);

    if (wid == 0) {
        asm volatile(
            "tcgen05.alloc.cta_group::1.sync.aligned.shared::cta.b32 [%0], %1;"
            :: "r"(tmslot), "r"(128u) : "memory");
    }
    if (tid == 0)
        asm volatile("mbarrier.init.shared.b64 [%0], %1;" :: "r"(mbar_a), "r"(1u) : "memory");
    if (tid < DD) {
        sb[tid] = bias[tid];
        if (LAYER == 2) { slw[tid] = lnw[tid]; slb[tid] = lnb[tid]; }
    }

    // ---- async loads, 2 groups: {B, Ahi} then {Alo} ----
    int rr[16], cc[16], so[16];
    #pragma unroll
    for (int it = 0; it < 16; it++) {
        int c = tid + it * 256;
        rr[it] = c >> 5; cc[it] = (c & 31) * 8;
        so[it] = sw_chunk(rr[it], cc[it]);
    }
    #pragma unroll
    for (int it = 0; it < 16; it++)
        cp16(dsm_u + SM_B + so[it], Bhi + rr[it] * 256 + cc[it]);
    #pragma unroll
    for (int it = 0; it < 16; it++) {
        int gr = row0 + rr[it]; if (gr >= NN) gr = 0;   // clamp: rows never stored
        size_t rb = (size_t)gr * DD;
        const __nv_bfloat16* ph = (cc[it] < DD) ? (g_mhi + rb + cc[it]) : (Ahh + rb + cc[it] - DD);
        cp16(dsm_u + SM_AHI + so[it], ph);
    }
    asm volatile("cp.async.commit_group;" ::: "memory");     // group: B + Ahi
    #pragma unroll
    for (int it = 0; it < 16; it++) {
        int gr = row0 + rr[it]; if (gr >= NN) gr = 0;
        size_t rb = (size_t)gr * DD;
        const __nv_bfloat16* pl = (cc[it] < DD) ? (g_mlo + rb + cc[it]) : (Ahl + rb + cc[it] - DD);
        cp16(dsm_u + SM_ALO + so[it], pl);
    }
    asm volatile("cp.async.commit_group;" ::: "memory");     // group: Alo

    __syncthreads();   // alloc + mbar init visible
    uint32_t tmem;
    asm volatile("ld.shared.b32 %0, [%1];" : "=r"(tmem) : "r"(tmslot));

    uint64_t dAhi = mk_desc(dsm_u + SM_AHI);
    uint64_t dAlo = mk_desc(dsm_u + SM_ALO);
    uint64_t dB   = mk_desc(dsm_u + SM_B);

    // ---- phase A1: Ahi*Bhi (Alo still streaming in) ----
    asm volatile("cp.async.wait_group 1;" ::: "memory");
    __syncthreads();
    if (tid == 0) {
        asm volatile("fence.proxy.async.shared::cta;" ::: "memory");
        #pragma unroll
        for (int t = 0; t < 16; t++)
            mma_bf16_ss(tmem, dAhi + koff(t), dB + koff(t), t > 0);
    }
    // ---- phase A2: Alo*Bhi ----
    asm volatile("cp.async.wait_group 0;" ::: "memory");
    __syncthreads();
    if (tid == 0) {
        asm volatile("fence.proxy.async.shared::cta;" ::: "memory");
        #pragma unroll
        for (int t = 0; t < 16; t++)
            mma_bf16_ss(tmem, dAlo + koff(t), dB + koff(t), 1);
        asm volatile(
            "tcgen05.commit.cta_group::1.mbarrier::arrive::one.shared::cluster.b64 [%0];"
            :: "r"(mbar_a) : "memory");
    }

    // ---- preload Blo into registers under the phase-A shadow ----
    uint4 bl[16];
    #pragma unroll
    for (int it = 0; it < 16; it++)
        bl[it] = *(const uint4*)(Blo + rr[it] * 256 + cc[it]);

    mbar_wait(mbar_a, 0);

    // ---- swap B -> Blo (STS only) ----
    #pragma unroll
    for (int it = 0; it < 16; it++)
        *(uint4*)(dsm + SM_B + so[it]) = bl[it];
    __syncthreads();

    // ---- phase B: Ahi*Blo ----
    if (tid == 0) {
        asm volatile("fence.proxy.async.shared::cta;" ::: "memory");
        #pragma unroll
        for (int t = 0; t < 16; t++)
            mma_bf16_ss(tmem, dAhi + koff(t), dB + koff(t), 1);
        asm volatile(
            "tcgen05.commit.cta_group::1.mbarrier::arrive::one.shared::cluster.b64 [%0];"
            :: "r"(mbar_a) : "memory");
    }
    mbar_wait(mbar_a, 1);
    asm volatile("tcgen05.fence::after_thread_sync;" ::: "memory");

    // ---- epilogue: warp w -> rows (w&3)*32+lane, cols (w>>2)*64..+63 ----
    const int sub = wid & 3, half = wid >> 2;
    const int cb = half * 64;
    uint32_t dr[64];
    #define LD32(p, a) \
        asm volatile("tcgen05.ld.sync.aligned.32x32b.x32.b32 " \
            "{%0,%1,%2,%3,%4,%5,%6,%7,%8,%9,%10,%11,%12,%13,%14,%15," \
            "%16,%17,%18,%19,%20,%21,%22,%23,%24,%25,%26,%27,%28,%29,%30,%31}, [%32];" \
            : "=r"((p)[0]),"=r"((p)[1]),"=r"((p)[2]),"=r"((p)[3]),"=r"((p)[4]),"=r"((p)[5]), \
              "=r"((p)[6]),"=r"((p)[7]),"=r"((p)[8]),"=r"((p)[9]),"=r"((p)[10]),"=r"((p)[11]), \
              "=r"((p)[12]),"=r"((p)[13]),"=r"((p)[14]),"=r"((p)[15]),"=r"((p)[16]),"=r"((p)[17]), \
              "=r"((p)[18]),"=r"((p)[19]),"=r"((p)[20]),"=r"((p)[21]),"=r"((p)[22]),"=r"((p)[23]), \
              "=r"((p)[24]),"=r"((p)[25]),"=r"((p)[26]),"=r"((p)[27]),"=r"((p)[28]),"=r"((p)[29]), \
              "=r"((p)[30]),"=r"((p)[31]) : "r"(a))
    LD32(dr,      tmem + cb);
    LD32(dr + 32, tmem + cb + 32);
    asm volatile("tcgen05.wait::ld.sync.aligned;" ::: "memory");
    #undef LD32

    const int r = sub * 32 + lane;          // local row
    const int gr = row0 + r;
    float v[64];
    float s = 0.f, sq = 0.f;
    #pragma unroll
    for (int j = 0; j < 64; j++) {
        float f = fmaxf(__uint_as_float(dr[j]) + sb[cb + j], 0.f);
        v[j] = f;
        s += f; sq += f * f;
    }

    if (LAYER == 1) {
        if (gr < NN) {
            size_t rbase = (size_t)gr * DD + cb;
            #pragma unroll
            for (int c8 = 0; c8 < 8; c8++) {
                __nv_bfloat16 h[8], l[8];
                #pragma unroll
                for (int q = 0; q < 8; q++) split1(v[c8 * 8 + q], h[q], l[q]);
                uint4 uh = make_uint4(pk2(h[0],h[1]), pk2(h[2],h[3]),
                                      pk2(h[4],h[5]), pk2(h[6],h[7]));
                uint4 ul = make_uint4(pk2(l[0],l[1]), pk2(l[2],l[3]),
                                      pk2(l[4],l[5]), pk2(l[6],l[7]));
                *(uint4*)(g_h1hi + rbase + c8 * 8) = uh;
                *(uint4*)(g_h1lo + rbase + c8 * 8) = ul;
            }
        }
    } else {
        psS[half][r] = s;
        psQ[half][r] = sq;
        __syncthreads();
        float st = psS[0][r] + psS[1][r];
        float qt = psQ[0][r] + psQ[1][r];
        float mu  = st * (1.0f / DD);
        float var = qt * (1.0f / DD) - mu * mu;
        float rs  = rsqrtf(var + 1e-5f);
        if (gr < NN) {
            size_t rbase = (size_t)gr * DD + cb;
            #pragma unroll
            for (int c4 = 0; c4 < 16; c4++) {
                float4 o;
                o.x = (v[c4*4+0] - mu) * rs * slw[cb+c4*4+0] + slb[cb+c4*4+0];
                o.y = (v[c4*4+1] - mu) * rs * slw[cb+c4*4+1] + slb[cb+c4*4+1];
                o.z = (v[c4*4+2] - mu) * rs * slw[cb+c4*4+2] + slb[cb+c4*4+2];
                o.w = (v[c4*4+3] - mu) * rs * slw[cb+c4*4+3] + slb[cb+c4*4+3];
                *(float4*)(outp + rbase + c4 * 4) = o;
            }
        }
    }

    __syncthreads();
    if (tid == 0)
        asm volatile("mbarrier.inval.shared.b64 [%0];" :: "r"(mbar_a) : "memory");
    __syncthreads();
    if (wid == 0) {
        asm volatile("tcgen05.dealloc.cta_group::1.sync.aligned.b32 %0, %1;"
                     :: "r"(tmem), "r"(128u));
        asm volatile("tcgen05.relinquish_alloc_permit.cta_group::1.sync.aligned;");
    }
#endif  // TC5
}

// ---------------- launch ----------------
extern "C" void kernel_launch(void* const* d_in, const int* in_sizes, int n_in,
                              void* d_out, int out_size) {
    const float* x   = (const float*)d_in[0];
    const void*  ei  = d_in[1];
    const float* W1l = (const float*)d_in[2];
    const float* b1l = (const float*)d_in[3];
    const float* W1r = (const float*)d_in[4];
    const float* W2l = (const float*)d_in[5];
    const float* b2l = (const float*)d_in[6];
    const float* W2r = (const float*)d_in[7];
    const float* lnw = (const float*)d_in[8];
    const float* lnb = (const float*)d_in[9];
    float* out = (float*)d_out;

    cudaFuncSetAttribute(k_mma<1>, cudaFuncAttributeMaxDynamicSharedMemorySize, DSMEM);
    cudaFuncSetAttribute(k_mma<2>, cudaFuncAttributeMaxDynamicSharedMemorySize, DSMEM);

    const int ph_blocks  = WPREP_BLOCKS + XS_BLOCKS + HIST_BLOCKS;
    const int mma_blocks = (NN + 127) / 128;                    // 391

    k_zero<<<(NN + 255) / 256, 256>>>((const unsigned long long*)ei);
    k_ph<<<ph_blocks, 256>>>(x, ei, W1l, W1r, W2l, W2r);
    k_scan1<<<SCAN_BLOCKS, 1024>>>();
    k_scatter<<<(NE + 255) / 256, 256>>>(ei);

    // layer 1
    k_agg<1><<<(NN * 32 + 255) / 256, 256>>>(x);
    k_mma<1><<<mma_blocks, 256, DSMEM>>>(b1l, nullptr, nullptr, out);

    // layer 2 (+ LayerNorm)
    k_agg<2><<<(NN * 32 + 255) / 256, 256>>>(x);
    k_mma<2><<<mma_blocks, 256, DSMEM>>>(b2l, lnw, lnb, out);
}

// round 10
// speedup vs baseline: 1.7779x; 1.0225x over previous
#include <cuda_runtime.h>
#include <cuda_bf16.h>
#include <cstdint>

#define NN 50000
#define NE 800000
#define DD 128
#define SCAN_BLOCKS 25

// tcgen05 is only legal on arch-specific targets (sm_103a / sm_100a).
// The harness also compiles a plain compute_103 pass -> give it a stub body.
#if !defined(__CUDA_ARCH__) || defined(__CUDA_ARCH_FEAT_SM103_ALL) || \
    defined(__CUDA_ARCH_FEAT_SM100_ALL) || defined(__CUDA_ARCH_SPECIFIC__)
#define TC5 1
#else
#define TC5 0
#endif

// ---------------- scratch (no allocs -> device globals) ----------------
__device__ int   g_deg[NN];
__device__ int   g_off[NN];      // intra-block exclusive; final = g_off[i]+pref(bsum)[i>>11]
__device__ int   g_rank[NE];     // per-edge slot within its dst segment (from hist atomic)
__device__ int   g_adj[NE];
__device__ int   g_bsum[32];     // raw per-block sums (prefix computed by consumers)
__device__ int   g_is32;
__device__ __align__(16) __nv_bfloat16  g_mhi[(size_t)NN * DD];
__device__ __align__(16) __nv_bfloat16  g_mlo[(size_t)NN * DD];
__device__ __align__(16) __nv_bfloat16  g_h1hi[(size_t)NN * DD];
__device__ __align__(16) __nv_bfloat16  g_h1lo[(size_t)NN * DD];
__device__ __align__(16) __nv_bfloat16  g_B1hi[DD * 2 * DD];  // [j][k] k-major, K=256
__device__ __align__(16) __nv_bfloat16  g_B1lo[DD * 2 * DD];
__device__ __align__(16) __nv_bfloat16  g_B2hi[DD * 2 * DD];
__device__ __align__(16) __nv_bfloat16  g_B2lo[DD * 2 * DD];

// ---------------- small helpers ----------------
__device__ __forceinline__ uint32_t s2u32(const void* p) {
    uint32_t a;
    asm("{ .reg .u64 t; cvta.to.shared.u64 t, %1; cvt.u32.u64 %0, t; }" : "=r"(a) : "l"(p));
    return a;
}
__device__ __forceinline__ unsigned pk2(__nv_bfloat16 a, __nv_bfloat16 b) {
    unsigned short ua = *(unsigned short*)&a, ub = *(unsigned short*)&b;
    return (unsigned)ua | ((unsigned)ub << 16);
}
__device__ __forceinline__ void split1(float v, __nv_bfloat16& h, __nv_bfloat16& l) {
    h = __float2bfloat16_rn(v);
    l = __float2bfloat16_rn(v - __bfloat162float(h));
}
__device__ __forceinline__ void addpair(float& a0, float& a1, unsigned h, unsigned l) {
    float2 fh = __bfloat1622float2(*(__nv_bfloat162*)&h);
    float2 fl = __bfloat1622float2(*(__nv_bfloat162*)&l);
    a0 += fh.x + fl.x;
    a1 += fh.y + fl.y;
}
__device__ __forceinline__ int load_src(const void* ei, int e) {
    return g_is32 ? ((const int*)ei)[e] : (int)((const long long*)ei)[e];
}
__device__ __forceinline__ int load_dst(const void* ei, int e) {
    return g_is32 ? ((const int*)ei)[NE + e] : (int)((const long long*)ei)[NE + e];
}

// per-block exclusive prefix of g_bsum into smem (one warp, shfl scan)
#define BSUM_PREF(spref) do {                                             \
    if (threadIdx.x < 32) {                                               \
        int gg = (threadIdx.x < SCAN_BLOCKS) ? g_bsum[threadIdx.x] : 0;   \
        int vv = gg;                                                      \
        _Pragma("unroll")                                                 \
        for (int oo = 1; oo < 32; oo <<= 1) {                             \
            int uu = __shfl_up_sync(0xffffffffu, vv, oo);                 \
            if ((int)threadIdx.x >= oo) vv += uu;                         \
        }                                                                 \
        (spref)[threadIdx.x] = vv - gg;                                   \
    }                                                                     \
    __syncthreads();                                                      \
} while (0)

// ---------------- zero + dtype detect (must precede fused prep/hist) ----------------
__global__ void k_zero(const unsigned long long* __restrict__ ei) {
    int i = blockIdx.x * blockDim.x + threadIdx.x;
    if (i < NN) g_deg[i] = 0;
    if (i == 0) {
        int bad = 0;
        #pragma unroll
        for (int k = 0; k < 16; k++)
            if (ei[k] >= (unsigned long long)NN) bad = 1;
        g_is32 = bad;
    }
}

// ---------------- fused: weight split | hist(+rank) as block ranges ----------------
#define WPREP_BLOCKS 128
#define HIST_BLOCKS  ((NE + 255) / 256)                // 3125
__global__ void k_ph(const void* __restrict__ ei,
                     const float* __restrict__ W1l, const float* __restrict__ W1r,
                     const float* __restrict__ W2l, const float* __restrict__ W2r) {
    int b = blockIdx.x;
    if (b < WPREP_BLOCKS) {
        int id = b * 256 + threadIdx.x;  // < 32768
        int j = id >> 8, k = id & 255;
        float w1 = (k < DD) ? W1l[j * DD + k] : W1r[j * DD + k - DD];
        float w2 = (k < DD) ? W2l[j * DD + k] : W2r[j * DD + k - DD];
        __nv_bfloat16 h, l;
        split1(w1, h, l); g_B1hi[id] = h; g_B1lo[id] = l;
        split1(w2, h, l); g_B2hi[id] = h; g_B2lo[id] = l;
    } else {
        int e = (b - WPREP_BLOCKS) * 256 + threadIdx.x;
        if (e < NE) {
            int dst = load_dst(ei, e);
            if ((unsigned)dst < (unsigned)NN)
                g_rank[e] = atomicAdd(&g_deg[dst], 1);
        }
    }
}

// intra-block exclusive scan; raw block totals to g_bsum (no global tail)
__global__ void k_scan1() {
    __shared__ int sc[1024];
    int t = threadIdx.x;
    int base = blockIdx.x * 2048;
    int i0 = base + 2 * t, i1 = i0 + 1;
    int a = (i0 < NN) ? g_deg[i0] : 0;
    int b = (i1 < NN) ? g_deg[i1] : 0;
    sc[t] = a + b;
    __syncthreads();
    #pragma unroll
    for (int off = 1; off < 1024; off <<= 1) {
        int v = (t >= off) ? sc[t - off] : 0;
        __syncthreads();
        sc[t] += v;
        __syncthreads();
    }
    int excl = sc[t] - (a + b);
    if (i0 < NN) g_off[i0] = excl;
    if (i1 < NN) g_off[i1] = excl + a;
    if (t == 1023) g_bsum[blockIdx.x] = sc[t];
}

// scatter: no atomics (rank precomputed in hist)
__global__ void k_scatter(const void* __restrict__ ei) {
    __shared__ int spref[32];
    BSUM_PREF(spref);
    int e = blockIdx.x * blockDim.x + threadIdx.x;
    if (e < NE) {
        int dst = load_dst(ei, e);
        int src = load_src(ei, e);
        if ((unsigned)dst < (unsigned)NN && (unsigned)src < (unsigned)NN) {
            int pos = g_off[dst] + spref[dst >> 11] + g_rank[e];
            if ((unsigned)pos < (unsigned)NE) g_adj[pos] = src;
        }
    }
}

// ---------------- mean aggregation: one warp per node; writes bf16 hi/lo ----------------
template <int LAYER>
__global__ void __launch_bounds__(256) k_agg(const float* __restrict__ x) {
    __shared__ int spref[32];
    BSUM_PREF(spref);
    int warp = (blockIdx.x * blockDim.x + threadIdx.x) >> 5;
    int lane = threadIdx.x & 31;
    if (warp >= NN) return;
    int beg = g_off[warp] + spref[(warp >> 11) & 31];
    int d   = g_deg[warp];
    float4 acc = make_float4(0.f, 0.f, 0.f, 0.f);
    for (int b = 0; b < d; b += 32) {
        int m  = min(32, d - b);
        int sl = (lane < m) ? g_adj[beg + b + lane] : 0;
        #pragma unroll 4
        for (int j = 0; j < m; j++) {
            int s = __shfl_sync(0xffffffffu, sl, j);
            if (LAYER == 1) {
                const float4 v = __ldg((const float4*)(x + (size_t)s * DD) + lane);
                acc.x += v.x; acc.y += v.y; acc.z += v.z; acc.w += v.w;
            } else {
                const uint2 vh = __ldg((const uint2*)(g_h1hi + (size_t)s * DD) + lane);
                const uint2 vl = __ldg((const uint2*)(g_h1lo + (size_t)s * DD) + lane);
                addpair(acc.x, acc.y, vh.x, vl.x);
                addpair(acc.z, acc.w, vh.y, vl.y);
            }
        }
    }
    float inv = 1.0f / (float)max(d, 1);
    acc.x *= inv; acc.y *= inv; acc.z *= inv; acc.w *= inv;
    __nv_bfloat16 h0, h1, h2, h3, l0, l1, l2, l3;
    split1(acc.x, h0, l0); split1(acc.y, h1, l1);
    split1(acc.z, h2, l2); split1(acc.w, h3, l3);
    size_t rb = (size_t)warp * DD;
    ((uint2*)(g_mhi + rb))[lane] = make_uint2(pk2(h0, h1), pk2(h2, h3));
    ((uint2*)(g_mlo + rb))[lane] = make_uint2(pk2(l0, l1), pk2(l2, l3));
}

// ================= tcgen05 GEMM =================
// Per CTA: 128 rows, N=128, K=256. SS bf16 MMA, fp32 TMEM accum.
// D = Ahi*Bhi + Alo*Bhi + Ahi*Blo  (2-way bf16 split of fp32)
// smem: [1KB slack] A_hi 64KB | A_lo 64KB | B 64KB (Bhi, then Blo via reg preload).
// Layer 1: A-right half (cols 128..255) split from fp32 x IN-KERNEL (no xsplit pass).

#define SM_AHI 0
#define SM_ALO 65536
#define SM_B   131072
#define DSMEM  (196608 + 1024)

static constexpr uint32_t IDESC_BF16 =
    (1u << 4) | (1u << 7) | (1u << 10) | ((128u / 8) << 17) | ((128u / 16) << 24);

// blocked SW128 atom layout: atom = 8 rows x 64 bf16 (1024B); 16 atom-rows, 4 atom-cols
__device__ __forceinline__ int sw_chunk(int row, int col) {   // col multiple of 8
    int byte = ((row >> 3) + (col >> 6) * 16) * 1024 + (row & 7) * 128 + (col & 63) * 2;
    return byte ^ ((byte >> 3) & 0x70);
}
__device__ __forceinline__ uint64_t mk_desc(uint32_t addr) {
    const uint64_t base = (2ull << 61) | (1ull << 46) | (64ull << 32) | (1ull << 16);
    return base | ((uint64_t)(addr >> 4) & 0x3FFF);
}
__device__ __forceinline__ uint64_t koff(int t) {   // K16-step t=0..15
    return (uint64_t)(((t >> 2) * 1024) + (t & 3) * 2);
}

#if TC5
__device__ __forceinline__ void mma_bf16_ss(uint32_t d, uint64_t ad, uint64_t bd,
                                            uint32_t en) {
    asm volatile(
        "{\n\t.reg .pred p;\n\tsetp.ne.u32 p, %4, 0;\n\t"
        "tcgen05.mma.cta_group::1.kind::f16 [%0], %1, %2, %3, {%5, %5, %5, %5}, p;\n\t}"
        :: "r"(d), "l"(ad), "l"(bd), "r"(IDESC_BF16), "r"(en), "r"(0u) : "memory");
}
__device__ __forceinline__ void cp16(uint32_t saddr, const void* gaddr) {
    asm volatile("cp.async.cg.shared.global [%0], [%1], 16;"
                 :: "r"(saddr), "l"(gaddr) : "memory");
}
#endif
__device__ __forceinline__ void mbar_wait(uint32_t mbar, uint32_t parity) {
    uint32_t done;
    asm volatile(
        "{\n\t.reg .pred p;\n\t"
        "mbarrier.try_wait.parity.acquire.cta.shared::cta.b64 p, [%1], %2;\n\t"
        "selp.b32 %0, 1, 0, p;\n\t}"
        : "=r"(done) : "r"(mbar), "r"(parity) : "memory");
    if (!done) {
        asm volatile(
            "{\n\t.reg .pred P1;\n\t"
            "WL_%=:\n\t"
            "mbarrier.try_wait.parity.acquire.cta.shared::cta.b64 P1, [%0], %1, 0x989680;\n\t"
            "@P1 bra.uni WD_%=;\n\t"
            "bra.uni WL_%=;\n\t"
            "WD_%=:\n\t}"
            :: "r"(mbar), "r"(parity) : "memory");
    }
}

template <int LAYER>
__global__ void __launch_bounds__(256) k_mma(
    const float* __restrict__ xin, const float* __restrict__ bias,
    const float* __restrict__ lnw, const float* __restrict__ lnb,
    float* __restrict__ outp)
{
#if TC5
    extern __shared__ char dsm_raw[];
    __shared__ uint32_t s_tmem;
    __shared__ __align__(8) unsigned long long s_mbar;
    __shared__ float sb[DD], slw[DD], slb[DD];
    __shared__ float psS[2][DD], psQ[2][DD];

    const uint32_t raw_u = s2u32(dsm_raw);
    const uint32_t dsm_u = (raw_u + 1023u) & ~1023u;   // SW128 needs 1KB-aligned base
    char* dsm = dsm_raw + (dsm_u - raw_u);

    const int tid  = threadIdx.x;
    const int wid  = tid >> 5;
    const int lane = tid & 31;
    const int row0 = blockIdx.x * 128;

    const __nv_bfloat16* Bhi = (LAYER == 1) ? g_B1hi : g_B2hi;
    const __nv_bfloat16* Blo = (LAYER == 1) ? g_B1lo : g_B2lo;

    uint32_t mbar_a = s2u32(&s_mbar);
    uint32_t tmslot = s2u32(&s_tmem);

    if (wid == 0) {
        asm volatile(
            "tcgen05.alloc.cta_group::1.sync.aligned.shared::cta.b32 [%0], %1;"
            :: "r"(tmslot), "r"(128u) : "memory");
    }
    if (tid == 0)
        asm volatile("mbarrier.init.shared.b64 [%0], %1;" :: "r"(mbar_a), "r"(1u) : "memory");
    if (tid < DD) {
        sb[tid] = bias[tid];
        if (LAYER == 2) { slw[tid] = lnw[tid]; slb[tid] = lnb[tid]; }
    }

    // ---- chunk map: 16 chunks/thread of 16B; row=c>>5, col=(c&31)*8 ----
    int rr[16], cc[16], so[16];
    #pragma unroll
    for (int it = 0; it < 16; it++) {
        int c = tid + it * 256;
        rr[it] = c >> 5; cc[it] = (c & 31) * 8;
        so[it] = sw_chunk(rr[it], cc[it]);
    }

    // group 1: B(hi) + A-hi (mean always async; right half async only for layer 2)
    #pragma unroll
    for (int it = 0; it < 16; it++)
        cp16(dsm_u + SM_B + so[it], Bhi + rr[it] * 256 + cc[it]);
    #pragma unroll
    for (int it = 0; it < 16; it++) {
        int gr = row0 + rr[it]; if (gr >= NN) gr = 0;   // clamp: rows never stored
        size_t rb = (size_t)gr * DD;
        if (cc[it] < DD)
            cp16(dsm_u + SM_AHI + so[it], g_mhi + rb + cc[it]);
        else if (LAYER == 2)
            cp16(dsm_u + SM_AHI + so[it], g_h1hi + rb + cc[it] - DD);
    }
    asm volatile("cp.async.commit_group;" ::: "memory");     // group: B + A-hi
    #pragma unroll
    for (int it = 0; it < 16; it++) {
        int gr = row0 + rr[it]; if (gr >= NN) gr = 0;
        size_t rb = (size_t)gr * DD;
        if (cc[it] < DD)
            cp16(dsm_u + SM_ALO + so[it], g_mlo + rb + cc[it]);
        else if (LAYER == 2)
            cp16(dsm_u + SM_ALO + so[it], g_h1lo + rb + cc[it] - DD);
    }
    asm volatile("cp.async.commit_group;" ::: "memory");     // group: A-lo

    // layer 1: right half from fp32 x, split in registers, STS to both buffers
    if (LAYER == 1) {
        #pragma unroll
        for (int it = 0; it < 16; it++) {
            if (cc[it] >= DD) {
                int gr = row0 + rr[it]; if (gr >= NN) gr = 0;
                const float* xr = xin + (size_t)gr * DD + (cc[it] - DD);
                float4 a = *(const float4*)xr;
                float4 b = *(const float4*)(xr + 4);
                __nv_bfloat16 h[8], l[8];
                split1(a.x, h[0], l[0]); split1(a.y, h[1], l[1]);
                split1(a.z, h[2], l[2]); split1(a.w, h[3], l[3]);
                split1(b.x, h[4], l[4]); split1(b.y, h[5], l[5]);
                split1(b.z, h[6], l[6]); split1(b.w, h[7], l[7]);
                *(uint4*)(dsm + SM_AHI + so[it]) =
                    make_uint4(pk2(h[0],h[1]), pk2(h[2],h[3]), pk2(h[4],h[5]), pk2(h[6],h[7]));
                *(uint4*)(dsm + SM_ALO + so[it]) =
                    make_uint4(pk2(l[0],l[1]), pk2(l[2],l[3]), pk2(l[4],l[5]), pk2(l[6],l[7]));
            }
        }
    }

    __syncthreads();   // alloc + mbar init visible
    uint32_t tmem;
    asm volatile("ld.shared.b32 %0, [%1];" : "=r"(tmem) : "r"(tmslot));

    uint64_t dAhi = mk_desc(dsm_u + SM_AHI);
    uint64_t dAlo = mk_desc(dsm_u + SM_ALO);
    uint64_t dB   = mk_desc(dsm_u + SM_B);

    // ---- phase A1: Ahi*Bhi (A-lo may still be streaming) ----
    asm volatile("cp.async.wait_group 1;" ::: "memory");
    __syncthreads();
    if (tid == 0) {
        asm volatile("fence.proxy.async.shared::cta;" ::: "memory");
        #pragma unroll
        for (int t = 0; t < 16; t++)
            mma_bf16_ss(tmem, dAhi + koff(t), dB + koff(t), t > 0);
    }
    // ---- phase A2: Alo*Bhi ----
    asm volatile("cp.async.wait_group 0;" ::: "memory");
    __syncthreads();
    if (tid == 0) {
        asm volatile("fence.proxy.async.shared::cta;" ::: "memory");
        #pragma unroll
        for (int t = 0; t < 16; t++)
            mma_bf16_ss(tmem, dAlo + koff(t), dB + koff(t), 1);
        asm volatile(
            "tcgen05.commit.cta_group::1.mbarrier::arrive::one.shared::cluster.b64 [%0];"
            :: "r"(mbar_a) : "memory");
    }

    // ---- preload Blo into registers under the phase-A shadow ----
    uint4 bl[16];
    #pragma unroll
    for (int it = 0; it < 16; it++)
        bl[it] = *(const uint4*)(Blo + rr[it] * 256 + cc[it]);

    mbar_wait(mbar_a, 0);

    // ---- swap B -> Blo (STS only) ----
    #pragma unroll
    for (int it = 0; it < 16; it++)
        *(uint4*)(dsm + SM_B + so[it]) = bl[it];
    __syncthreads();

    // ---- phase B: Ahi*Blo ----
    if (tid == 0) {
        asm volatile("fence.proxy.async.shared::cta;" ::: "memory");
        #pragma unroll
        for (int t = 0; t < 16; t++)
            mma_bf16_ss(tmem, dAhi + koff(t), dB + koff(t), 1);
        asm volatile(
            "tcgen05.commit.cta_group::1.mbarrier::arrive::one.shared::cluster.b64 [%0];"
            :: "r"(mbar_a) : "memory");
    }
    mbar_wait(mbar_a, 1);
    asm volatile("tcgen05.fence::after_thread_sync;" ::: "memory");

    // ---- epilogue: warp w -> rows (w&3)*32+lane, cols (w>>2)*64..+63 ----
    const int sub = wid & 3, half = wid >> 2;
    const int cb = half * 64;
    uint32_t dr[64];
    #define LD32(p, a) \
        asm volatile("tcgen05.ld.sync.aligned.32x32b.x32.b32 " \
            "{%0,%1,%2,%3,%4,%5,%6,%7,%8,%9,%10,%11,%12,%13,%14,%15," \
            "%16,%17,%18,%19,%20,%21,%22,%23,%24,%25,%26,%27,%28,%29,%30,%31}, [%32];" \
            : "=r"((p)[0]),"=r"((p)[1]),"=r"((p)[2]),"=r"((p)[3]),"=r"((p)[4]),"=r"((p)[5]), \
              "=r"((p)[6]),"=r"((p)[7]),"=r"((p)[8]),"=r"((p)[9]),"=r"((p)[10]),"=r"((p)[11]), \
              "=r"((p)[12]),"=r"((p)[13]),"=r"((p)[14]),"=r"((p)[15]),"=r"((p)[16]),"=r"((p)[17]), \
              "=r"((p)[18]),"=r"((p)[19]),"=r"((p)[20]),"=r"((p)[21]),"=r"((p)[22]),"=r"((p)[23]), \
              "=r"((p)[24]),"=r"((p)[25]),"=r"((p)[26]),"=r"((p)[27]),"=r"((p)[28]),"=r"((p)[29]), \
              "=r"((p)[30]),"=r"((p)[31]) : "r"(a))
    LD32(dr,      tmem + cb);
    LD32(dr + 32, tmem + cb + 32);
    asm volatile("tcgen05.wait::ld.sync.aligned;" ::: "memory");
    #undef LD32

    const int r = sub * 32 + lane;          // local row
    const int gr = row0 + r;
    float v[64];
    float s = 0.f, sq = 0.f;
    #pragma unroll
    for (int j = 0; j < 64; j++) {
        float f = fmaxf(__uint_as_float(dr[j]) + sb[cb + j], 0.f);
        v[j] = f;
        s += f; sq += f * f;
    }

    if (LAYER == 1) {
        if (gr < NN) {
            size_t rbase = (size_t)gr * DD + cb;
            #pragma unroll
            for (int c8 = 0; c8 < 8; c8++) {
                __nv_bfloat16 h[8], l[8];
                #pragma unroll
                for (int q = 0; q < 8; q++) split1(v[c8 * 8 + q], h[q], l[q]);
                uint4 uh = make_uint4(pk2(h[0],h[1]), pk2(h[2],h[3]),
                                      pk2(h[4],h[5]), pk2(h[6],h[7]));
                uint4 ul = make_uint4(pk2(l[0],l[1]), pk2(l[2],l[3]),
                                      pk2(l[4],l[5]), pk2(l[6],l[7]));
                *(uint4*)(g_h1hi + rbase + c8 * 8) = uh;
                *(uint4*)(g_h1lo + rbase + c8 * 8) = ul;
            }
        }
    } else {
        psS[half][r] = s;
        psQ[half][r] = sq;
        __syncthreads();
        float st = psS[0][r] + psS[1][r];
        float qt = psQ[0][r] + psQ[1][r];
        float mu  = st * (1.0f / DD);
        float var = qt * (1.0f / DD) - mu * mu;
        float rs  = rsqrtf(var + 1e-5f);
        if (gr < NN) {
            size_t rbase = (size_t)gr * DD + cb;
            #pragma unroll
            for (int c4 = 0; c4 < 16; c4++) {
                float4 o;
                o.x = (v[c4*4+0] - mu) * rs * slw[cb+c4*4+0] + slb[cb+c4*4+0];
                o.y = (v[c4*4+1] - mu) * rs * slw[cb+c4*4+1] + slb[cb+c4*4+1];
                o.z = (v[c4*4+2] - mu) * rs * slw[cb+c4*4+2] + slb[cb+c4*4+2];
                o.w = (v[c4*4+3] - mu) * rs * slw[cb+c4*4+3] + slb[cb+c4*4+3];
                *(float4*)(outp + rbase + c4 * 4) = o;
            }
        }
    }

    __syncthreads();
    if (tid == 0)
        asm volatile("mbarrier.inval.shared.b64 [%0];" :: "r"(mbar_a) : "memory");
    __syncthreads();
    if (wid == 0) {
        asm volatile("tcgen05.dealloc.cta_group::1.sync.aligned.b32 %0, %1;"
                     :: "r"(tmem), "r"(128u));
        asm volatile("tcgen05.relinquish_alloc_permit.cta_group::1.sync.aligned;");
    }
#endif  // TC5
}

// ---------------- launch ----------------
extern "C" void kernel_launch(void* const* d_in, const int* in_sizes, int n_in,
                              void* d_out, int out_size) {
    const float* x   = (const float*)d_in[0];
    const void*  ei  = d_in[1];
    const float* W1l = (const float*)d_in[2];
    const float* b1l = (const float*)d_in[3];
    const float* W1r = (const float*)d_in[4];
    const float* W2l = (const float*)d_in[5];
    const float* b2l = (const float*)d_in[6];
    const float* W2r = (const float*)d_in[7];
    const float* lnw = (const float*)d_in[8];
    const float* lnb = (const float*)d_in[9];
    float* out = (float*)d_out;

    cudaFuncSetAttribute(k_mma<1>, cudaFuncAttributeMaxDynamicSharedMemorySize, DSMEM);
    cudaFuncSetAttribute(k_mma<2>, cudaFuncAttributeMaxDynamicSharedMemorySize, DSMEM);

    const int ph_blocks  = WPREP_BLOCKS + HIST_BLOCKS;
    const int mma_blocks = (NN + 127) / 128;                    // 391

    k_zero<<<(NN + 255) / 256, 256>>>((const unsigned long long*)ei);
    k_ph<<<ph_blocks, 256>>>(ei, W1l, W1r, W2l, W2r);
    k_scan1<<<SCAN_BLOCKS, 1024>>>();
    k_scatter<<<(NE + 255) / 256, 256>>>(ei);

    // layer 1
    k_agg<1><<<(NN * 32 + 255) / 256, 256>>>(x);
    k_mma<1><<<mma_blocks, 256, DSMEM>>>(x, b1l, nullptr, nullptr, out);

    // layer 2 (+ LayerNorm)
    k_agg<2><<<(NN * 32 + 255) / 256, 256>>>(x);
    k_mma<2><<<mma_blocks, 256, DSMEM>>>(x, b2l, lnw, lnb, out);
}

// round 11
// speedup vs baseline: 1.9384x; 1.0902x over previous
#include <cuda_runtime.h>
#include <cuda_bf16.h>
#include <cstdint>

#define NN 50000
#define NE 800000
#define DD 128
#define MAXDEG 128   // Poisson(16) max over 50k nodes ~45; 128 is overwhelmingly safe

// tcgen05 is only legal on arch-specific targets (sm_103a / sm_100a).
// The harness also compiles a plain compute_103 pass -> give it a stub body.
#if !defined(__CUDA_ARCH__) || defined(__CUDA_ARCH_FEAT_SM103_ALL) || \
    defined(__CUDA_ARCH_FEAT_SM100_ALL) || defined(__CUDA_ARCH_SPECIFIC__)
#define TC5 1
#else
#define TC5 0
#endif

// ---------------- scratch (no allocs -> device globals) ----------------
// g_deg must be 0 at entry to k_ph: static-init covers call 1; k_mma<2> re-zeros
// at the end of every call (agg2 is the last reader), keeping the invariant
// across CUDA-graph replays.
__device__ int   g_deg[NN];
__device__ int   g_adj[(size_t)NN * MAXDEG];   // slot table: adj[dst*128 + rank]
__device__ __align__(16) __nv_bfloat16  g_mhi[(size_t)NN * DD];
__device__ __align__(16) __nv_bfloat16  g_mlo[(size_t)NN * DD];
__device__ __align__(16) __nv_bfloat16  g_h1hi[(size_t)NN * DD];
__device__ __align__(16) __nv_bfloat16  g_h1lo[(size_t)NN * DD];
__device__ __align__(16) __nv_bfloat16  g_B1hi[DD * 2 * DD];  // [j][k] k-major, K=256
__device__ __align__(16) __nv_bfloat16  g_B1lo[DD * 2 * DD];
__device__ __align__(16) __nv_bfloat16  g_B2hi[DD * 2 * DD];
__device__ __align__(16) __nv_bfloat16  g_B2lo[DD * 2 * DD];

// ---------------- small helpers ----------------
__device__ __forceinline__ uint32_t s2u32(const void* p) {
    uint32_t a;
    asm("{ .reg .u64 t; cvta.to.shared.u64 t, %1; cvt.u32.u64 %0, t; }" : "=r"(a) : "l"(p));
    return a;
}
__device__ __forceinline__ unsigned pk2(__nv_bfloat16 a, __nv_bfloat16 b) {
    unsigned short ua = *(unsigned short*)&a, ub = *(unsigned short*)&b;
    return (unsigned)ua | ((unsigned)ub << 16);
}
__device__ __forceinline__ void split1(float v, __nv_bfloat16& h, __nv_bfloat16& l) {
    h = __float2bfloat16_rn(v);
    l = __float2bfloat16_rn(v - __bfloat162float(h));
}
__device__ __forceinline__ void addpair(float& a0, float& a1, unsigned h, unsigned l) {
    float2 fh = __bfloat1622float2(*(__nv_bfloat162*)&h);
    float2 fl = __bfloat1622float2(*(__nv_bfloat162*)&l);
    a0 += fh.x + fl.x;
    a1 += fh.y + fl.y;
}

// ---------------- fused: weight split | slot-table build (one pass, no CSR) ----------------
#define WPREP_BLOCKS 128
#define HIST_BLOCKS  ((NE + 255) / 256)                // 3125
__global__ void k_ph(const void* __restrict__ ei,
                     const float* __restrict__ W1l, const float* __restrict__ W1r,
                     const float* __restrict__ W2l, const float* __restrict__ W2r) {
    int b = blockIdx.x;
    if (b < WPREP_BLOCKS) {
        int id = b * 256 + threadIdx.x;  // < 32768
        int j = id >> 8, k = id & 255;
        float w1 = (k < DD) ? W1l[j * DD + k] : W1r[j * DD + k - DD];
        float w2 = (k < DD) ? W2l[j * DD + k] : W2r[j * DD + k - DD];
        __nv_bfloat16 h, l;
        split1(w1, h, l); g_B1hi[id] = h; g_B1lo[id] = l;
        split1(w2, h, l); g_B2hi[id] = h; g_B2lo[id] = l;
    } else {
        // local edge-dtype detect (JAX x64-off -> int32 likely). If the buffer is
        // int64, every word is a valid node id < NN. If int32, a 64-bit word holds
        // two ids and is >= 2^32 * id_hi (>= NN unless id_hi == 0, p ~ 2e-5/word).
        const unsigned long long* e64 = (const unsigned long long*)ei;
        bool is32 = false;
        #pragma unroll
        for (int k = 0; k < 8; k++)
            if (e64[k] >= (unsigned long long)NN) is32 = true;
        int e = (b - WPREP_BLOCKS) * 256 + threadIdx.x;
        if (e < NE) {
            int dst = is32 ? ((const int*)ei)[NE + e] : (int)((const long long*)ei)[NE + e];
            int src = is32 ? ((const int*)ei)[e]      : (int)((const long long*)ei)[e];
            if ((unsigned)dst < (unsigned)NN && (unsigned)src < (unsigned)NN) {
                int r = atomicAdd(&g_deg[dst], 1);
                if (r < MAXDEG) g_adj[(size_t)dst * MAXDEG + r] = src;
            }
        }
    }
}

// ---------------- mean aggregation: one warp per node; writes bf16 hi/lo ----------------
template <int LAYER>
__global__ void __launch_bounds__(256) k_agg(const float* __restrict__ x) {
    int warp = (blockIdx.x * blockDim.x + threadIdx.x) >> 5;
    int lane = threadIdx.x & 31;
    if (warp >= NN) return;
    const int* adjrow = g_adj + (size_t)warp * MAXDEG;
    int d = min(g_deg[warp], MAXDEG);
    float4 acc = make_float4(0.f, 0.f, 0.f, 0.f);
    for (int b = 0; b < d; b += 32) {
        int m  = min(32, d - b);
        int sl = (lane < m) ? adjrow[b + lane] : 0;
        #pragma unroll 4
        for (int j = 0; j < m; j++) {
            int s = __shfl_sync(0xffffffffu, sl, j);
            if (LAYER == 1) {
                const float4 v = __ldg((const float4*)(x + (size_t)s * DD) + lane);
                acc.x += v.x; acc.y += v.y; acc.z += v.z; acc.w += v.w;
            } else {
                const uint2 vh = __ldg((const uint2*)(g_h1hi + (size_t)s * DD) + lane);
                const uint2 vl = __ldg((const uint2*)(g_h1lo + (size_t)s * DD) + lane);
                addpair(acc.x, acc.y, vh.x, vl.x);
                addpair(acc.z, acc.w, vh.y, vl.y);
            }
        }
    }
    float inv = 1.0f / (float)max(d, 1);
    acc.x *= inv; acc.y *= inv; acc.z *= inv; acc.w *= inv;
    __nv_bfloat16 h0, h1, h2, h3, l0, l1, l2, l3;
    split1(acc.x, h0, l0); split1(acc.y, h1, l1);
    split1(acc.z, h2, l2); split1(acc.w, h3, l3);
    size_t rb = (size_t)warp * DD;
    ((uint2*)(g_mhi + rb))[lane] = make_uint2(pk2(h0, h1), pk2(h2, h3));
    ((uint2*)(g_mlo + rb))[lane] = make_uint2(pk2(l0, l1), pk2(l2, l3));
}

// ================= tcgen05 GEMM =================
// Per CTA: 128 rows, N=128, K=256. SS bf16 MMA, fp32 TMEM accum.
// D = Ahi*Bhi + Alo*Bhi + Ahi*Blo  (2-way bf16 split of fp32)
// smem: [1KB slack] A_hi 64KB | A_lo 64KB | B 64KB (Bhi, then Blo via reg preload).
// Layer 1: A-right half (cols 128..255) split from fp32 x IN-KERNEL.
// Layer 2: re-zeros g_deg at the end (next-call invariant).

#define SM_AHI 0
#define SM_ALO 65536
#define SM_B   131072
#define DSMEM  (196608 + 1024)

static constexpr uint32_t IDESC_BF16 =
    (1u << 4) | (1u << 7) | (1u << 10) | ((128u / 8) << 17) | ((128u / 16) << 24);

// blocked SW128 atom layout: atom = 8 rows x 64 bf16 (1024B); 16 atom-rows, 4 atom-cols
__device__ __forceinline__ int sw_chunk(int row, int col) {   // col multiple of 8
    int byte = ((row >> 3) + (col >> 6) * 16) * 1024 + (row & 7) * 128 + (col & 63) * 2;
    return byte ^ ((byte >> 3) & 0x70);
}
__device__ __forceinline__ uint64_t mk_desc(uint32_t addr) {
    const uint64_t base = (2ull << 61) | (1ull << 46) | (64ull << 32) | (1ull << 16);
    return base | ((uint64_t)(addr >> 4) & 0x3FFF);
}
__device__ __forceinline__ uint64_t koff(int t) {   // K16-step t=0..15
    return (uint64_t)(((t >> 2) * 1024) + (t & 3) * 2);
}

#if TC5
__device__ __forceinline__ void mma_bf16_ss(uint32_t d, uint64_t ad, uint64_t bd,
                                            uint32_t en) {
    asm volatile(
        "{\n\t.reg .pred p;\n\tsetp.ne.u32 p, %4, 0;\n\t"
        "tcgen05.mma.cta_group::1.kind::f16 [%0], %1, %2, %3, {%5, %5, %5, %5}, p;\n\t}"
        :: "r"(d), "l"(ad), "l"(bd), "r"(IDESC_BF16), "r"(en), "r"(0u) : "memory");
}
__device__ __forceinline__ void cp16(uint32_t saddr, const void* gaddr) {
    asm volatile("cp.async.cg.shared.global [%0], [%1], 16;"
                 :: "r"(saddr), "l"(gaddr) : "memory");
}
#endif
__device__ __forceinline__ void mbar_wait(uint32_t mbar, uint32_t parity) {
    uint32_t done;
    asm volatile(
        "{\n\t.reg .pred p;\n\t"
        "mbarrier.try_wait.parity.acquire.cta.shared::cta.b64 p, [%1], %2;\n\t"
        "selp.b32 %0, 1, 0, p;\n\t}"
        : "=r"(done) : "r"(mbar), "r"(parity) : "memory");
    if (!done) {
        asm volatile(
            "{\n\t.reg .pred P1;\n\t"
            "WL_%=:\n\t"
            "mbarrier.try_wait.parity.acquire.cta.shared::cta.b64 P1, [%0], %1, 0x989680;\n\t"
            "@P1 bra.uni WD_%=;\n\t"
            "bra.uni WL_%=;\n\t"
            "WD_%=:\n\t}"
            :: "r"(mbar), "r"(parity) : "memory");
    }
}

template <int LAYER>
__global__ void __launch_bounds__(256) k_mma(
    const float* __restrict__ xin, const float* __restrict__ bias,
    const float* __restrict__ lnw, const float* __restrict__ lnb,
    float* __restrict__ outp)
{
#if TC5
    extern __shared__ char dsm_raw[];
    __shared__ uint32_t s_tmem;
    __shared__ __align__(8) unsigned long long s_mbar;
    __shared__ float sb[DD], slw[DD], slb[DD];
    __shared__ float psS[2][DD], psQ[2][DD];

    const uint32_t raw_u = s2u32(dsm_raw);
    const uint32_t dsm_u = (raw_u + 1023u) & ~1023u;   // SW128 needs 1KB-aligned base
    char* dsm = dsm_raw + (dsm_u - raw_u);

    const int tid  = threadIdx.x;
    const int wid  = tid >> 5;
    const int lane = tid & 31;
    const int row0 = blockIdx.x * 128;

    const __nv_bfloat16* Bhi = (LAYER == 1) ? g_B1hi : g_B2hi;
    const __nv_bfloat16* Blo = (LAYER == 1) ? g_B1lo : g_B2lo;

    uint32_t mbar_a = s2u32(&s_mbar);
    uint32_t tmslot = s2u32(&s_tmem);

    if (wid == 0) {
        asm volatile(
            "tcgen05.alloc.cta_group::1.sync.aligned.shared::cta.b32 [%0], %1;"
            :: "r"(tmslot), "r"(128u) : "memory");
    }
    if (tid == 0)
        asm volatile("mbarrier.init.shared.b64 [%0], %1;" :: "r"(mbar_a), "r"(1u) : "memory");
    if (tid < DD) {
        sb[tid] = bias[tid];
        if (LAYER == 2) { slw[tid] = lnw[tid]; slb[tid] = lnb[tid]; }
    }

    // Layer 2: re-zero g_deg for the next call (agg2 was the last reader; this
    // kernel is stream-ordered after it). Grid 391*256 covers NN.
    if (LAYER == 2) {
        int zi = blockIdx.x * 256 + tid;
        if (zi < NN) g_deg[zi] = 0;
    }

    // ---- chunk map: 16 chunks/thread of 16B; row=c>>5, col=(c&31)*8 ----
    int rr[16], cc[16], so[16];
    #pragma unroll
    for (int it = 0; it < 16; it++) {
        int c = tid + it * 256;
        rr[it] = c >> 5; cc[it] = (c & 31) * 8;
        so[it] = sw_chunk(rr[it], cc[it]);
    }

    // group 1: B(hi) + A-hi (mean always async; right half async only for layer 2)
    #pragma unroll
    for (int it = 0; it < 16; it++)
        cp16(dsm_u + SM_B + so[it], Bhi + rr[it] * 256 + cc[it]);
    #pragma unroll
    for (int it = 0; it < 16; it++) {
        int gr = row0 + rr[it]; if (gr >= NN) gr = 0;   // clamp: rows never stored
        size_t rb = (size_t)gr * DD;
        if (cc[it] < DD)
            cp16(dsm_u + SM_AHI + so[it], g_mhi + rb + cc[it]);
        else if (LAYER == 2)
            cp16(dsm_u + SM_AHI + so[it], g_h1hi + rb + cc[it] - DD);
    }
    asm volatile("cp.async.commit_group;" ::: "memory");     // group: B + A-hi
    #pragma unroll
    for (int it = 0; it < 16; it++) {
        int gr = row0 + rr[it]; if (gr >= NN) gr = 0;
        size_t rb = (size_t)gr * DD;
        if (cc[it] < DD)
            cp16(dsm_u + SM_ALO + so[it], g_mlo + rb + cc[it]);
        else if (LAYER == 2)
            cp16(dsm_u + SM_ALO + so[it], g_h1lo + rb + cc[it] - DD);
    }
    asm volatile("cp.async.commit_group;" ::: "memory");     // group: A-lo

    // layer 1: right half from fp32 x, split in registers, STS to both buffers
    if (LAYER == 1) {
        #pragma unroll
        for (int it = 0; it < 16; it++) {
            if (cc[it] >= DD) {
                int gr = row0 + rr[it]; if (gr >= NN) gr = 0;
                const float* xr = xin + (size_t)gr * DD + (cc[it] - DD);
                float4 a = *(const float4*)xr;
                float4 b = *(const float4*)(xr + 4);
                __nv_bfloat16 h[8], l[8];
                split1(a.x, h[0], l[0]); split1(a.y, h[1], l[1]);
                split1(a.z, h[2], l[2]); split1(a.w, h[3], l[3]);
                split1(b.x, h[4], l[4]); split1(b.y, h[5], l[5]);
                split1(b.z, h[6], l[6]); split1(b.w, h[7], l[7]);
                *(uint4*)(dsm + SM_AHI + so[it]) =
                    make_uint4(pk2(h[0],h[1]), pk2(h[2],h[3]), pk2(h[4],h[5]), pk2(h[6],h[7]));
                *(uint4*)(dsm + SM_ALO + so[it]) =
                    make_uint4(pk2(l[0],l[1]), pk2(l[2],l[3]), pk2(l[4],l[5]), pk2(l[6],l[7]));
            }
        }
    }

    __syncthreads();   // alloc + mbar init visible
    uint32_t tmem;
    asm volatile("ld.shared.b32 %0, [%1];" : "=r"(tmem) : "r"(tmslot));

    uint64_t dAhi = mk_desc(dsm_u + SM_AHI);
    uint64_t dAlo = mk_desc(dsm_u + SM_ALO);
    uint64_t dB   = mk_desc(dsm_u + SM_B);

    // ---- phase A1: Ahi*Bhi (A-lo may still be streaming) ----
    asm volatile("cp.async.wait_group 1;" ::: "memory");
    __syncthreads();
    if (tid == 0) {
        asm volatile("fence.proxy.async.shared::cta;" ::: "memory");
        #pragma unroll
        for (int t = 0; t < 16; t++)
            mma_bf16_ss(tmem, dAhi + koff(t), dB + koff(t), t > 0);
    }
    // ---- phase A2: Alo*Bhi ----
    asm volatile("cp.async.wait_group 0;" ::: "memory");
    __syncthreads();
    if (tid == 0) {
        asm volatile("fence.proxy.async.shared::cta;" ::: "memory");
        #pragma unroll
        for (int t = 0; t < 16; t++)
            mma_bf16_ss(tmem, dAlo + koff(t), dB + koff(t), 1);
        asm volatile(
            "tcgen05.commit.cta_group::1.mbarrier::arrive::one.shared::cluster.b64 [%0];"
            :: "r"(mbar_a) : "memory");
    }

    // ---- preload Blo into registers under the phase-A shadow ----
    uint4 bl[16];
    #pragma unroll
    for (int it = 0; it < 16; it++)
        bl[it] = *(const uint4*)(Blo + rr[it] * 256 + cc[it]);

    mbar_wait(mbar_a, 0);

    // ---- swap B -> Blo (STS only) ----
    #pragma unroll
    for (int it = 0; it < 16; it++)
        *(uint4*)(dsm + SM_B + so[it]) = bl[it];
    __syncthreads();

    // ---- phase B: Ahi*Blo ----
    if (tid == 0) {
        asm volatile("fence.proxy.async.shared::cta;" ::: "memory");
        #pragma unroll
        for (int t = 0; t < 16; t++)
            mma_bf16_ss(tmem, dAhi + koff(t), dB + koff(t), 1);
        asm volatile(
            "tcgen05.commit.cta_group::1.mbarrier::arrive::one.shared::cluster.b64 [%0];"
            :: "r"(mbar_a) : "memory");
    }
    mbar_wait(mbar_a, 1);
    asm volatile("tcgen05.fence::after_thread_sync;" ::: "memory");

    // ---- epilogue: warp w -> rows (w&3)*32+lane, cols (w>>2)*64..+63 ----
    const int sub = wid & 3, half = wid >> 2;
    const int cb = half * 64;
    uint32_t dr[64];
    #define LD32(p, a) \
        asm volatile("tcgen05.ld.sync.aligned.32x32b.x32.b32 " \
            "{%0,%1,%2,%3,%4,%5,%6,%7,%8,%9,%10,%11,%12,%13,%14,%15," \
            "%16,%17,%18,%19,%20,%21,%22,%23,%24,%25,%26,%27,%28,%29,%30,%31}, [%32];" \
            : "=r"((p)[0]),"=r"((p)[1]),"=r"((p)[2]),"=r"((p)[3]),"=r"((p)[4]),"=r"((p)[5]), \
              "=r"((p)[6]),"=r"((p)[7]),"=r"((p)[8]),"=r"((p)[9]),"=r"((p)[10]),"=r"((p)[11]), \
              "=r"((p)[12]),"=r"((p)[13]),"=r"((p)[14]),"=r"((p)[15]),"=r"((p)[16]),"=r"((p)[17]), \
              "=r"((p)[18]),"=r"((p)[19]),"=r"((p)[20]),"=r"((p)[21]),"=r"((p)[22]),"=r"((p)[23]), \
              "=r"((p)[24]),"=r"((p)[25]),"=r"((p)[26]),"=r"((p)[27]),"=r"((p)[28]),"=r"((p)[29]), \
              "=r"((p)[30]),"=r"((p)[31]) : "r"(a))
    LD32(dr,      tmem + cb);
    LD32(dr + 32, tmem + cb + 32);
    asm volatile("tcgen05.wait::ld.sync.aligned;" ::: "memory");
    #undef LD32

    const int r = sub * 32 + lane;          // local row
    const int gr = row0 + r;
    float v[64];
    float s = 0.f, sq = 0.f;
    #pragma unroll
    for (int j = 0; j < 64; j++) {
        float f = fmaxf(__uint_as_float(dr[j]) + sb[cb + j], 0.f);
        v[j] = f;
        s += f; sq += f * f;
    }

    if (LAYER == 1) {
        if (gr < NN) {
            size_t rbase = (size_t)gr * DD + cb;
            #pragma unroll
            for (int c8 = 0; c8 < 8; c8++) {
                __nv_bfloat16 h[8], l[8];
                #pragma unroll
                for (int q = 0; q < 8; q++) split1(v[c8 * 8 + q], h[q], l[q]);
                uint4 uh = make_uint4(pk2(h[0],h[1]), pk2(h[2],h[3]),
                                      pk2(h[4],h[5]), pk2(h[6],h[7]));
                uint4 ul = make_uint4(pk2(l[0],l[1]), pk2(l[2],l[3]),
                                      pk2(l[4],l[5]), pk2(l[6],l[7]));
                *(uint4*)(g_h1hi + rbase + c8 * 8) = uh;
                *(uint4*)(g_h1lo + rbase + c8 * 8) = ul;
            }
        }
    } else {
        psS[half][r] = s;
        psQ[half][r] = sq;
        __syncthreads();
        float st = psS[0][r] + psS[1][r];
        float qt = psQ[0][r] + psQ[1][r];
        float mu  = st * (1.0f / DD);
        float var = qt * (1.0f / DD) - mu * mu;
        float rs  = rsqrtf(var + 1e-5f);
        if (gr < NN) {
            size_t rbase = (size_t)gr * DD + cb;
            #pragma unroll
            for (int c4 = 0; c4 < 16; c4++) {
                float4 o;
                o.x = (v[c4*4+0] - mu) * rs * slw[cb+c4*4+0] + slb[cb+c4*4+0];
                o.y = (v[c4*4+1] - mu) * rs * slw[cb+c4*4+1] + slb[cb+c4*4+1];
                o.z = (v[c4*4+2] - mu) * rs * slw[cb+c4*4+2] + slb[cb+c4*4+2];
                o.w = (v[c4*4+3] - mu) * rs * slw[cb+c4*4+3] + slb[cb+c4*4+3];
                *(float4*)(outp + rbase + c4 * 4) = o;
            }
        }
    }

    __syncthreads();
    if (tid == 0)
        asm volatile("mbarrier.inval.shared.b64 [%0];" :: "r"(mbar_a) : "memory");
    __syncthreads();
    if (wid == 0) {
        asm volatile("tcgen05.dealloc.cta_group::1.sync.aligned.b32 %0, %1;"
                     :: "r"(tmem), "r"(128u));
        asm volatile("tcgen05.relinquish_alloc_permit.cta_group::1.sync.aligned;");
    }
#endif  // TC5
}

// ---------------- launch ----------------
extern "C" void kernel_launch(void* const* d_in, const int* in_sizes, int n_in,
                              void* d_out, int out_size) {
    const float* x   = (const float*)d_in[0];
    const void*  ei  = d_in[1];
    const float* W1l = (const float*)d_in[2];
    const float* b1l = (const float*)d_in[3];
    const float* W1r = (const float*)d_in[4];
    const float* W2l = (const float*)d_in[5];
    const float* b2l = (const float*)d_in[6];
    const float* W2r = (const float*)d_in[7];
    const float* lnw = (const float*)d_in[8];
    const float* lnb = (const float*)d_in[9];
    float* out = (float*)d_out;

    cudaFuncSetAttribute(k_mma<1>, cudaFuncAttributeMaxDynamicSharedMemorySize, DSMEM);
    cudaFuncSetAttribute(k_mma<2>, cudaFuncAttributeMaxDynamicSharedMemorySize, DSMEM);

    const int ph_blocks  = WPREP_BLOCKS + HIST_BLOCKS;
    const int mma_blocks = (NN + 127) / 128;                    // 391

    // single-pass adjacency build (slot table, no CSR)
    k_ph<<<ph_blocks, 256>>>(ei, W1l, W1r, W2l, W2r);

    // layer 1
    k_agg<1><<<(NN * 32 + 255) / 256, 256>>>(x);
    k_mma<1><<<mma_blocks, 256, DSMEM>>>(x, b1l, nullptr, nullptr, out);

    // layer 2 (+ LayerNorm; re-zeros g_deg for next call)
    k_agg<2><<<(NN * 32 + 255) / 256, 256>>>(x);
    k_mma<2><<<mma_blocks, 256, DSMEM>>>(x, b2l, lnw, lnb, out);
}

// round 12
// speedup vs baseline: 1.9927x; 1.0280x over previous
#include <cuda_runtime.h>
#include <cuda_bf16.h>
#include <cstdint>

#define NN 50000
#define NE 800000
#define DD 128
#define MAXDEG 128   // Poisson(16) max over 50k nodes ~45; 128 is overwhelmingly safe

// tcgen05 is only legal on arch-specific targets (sm_103a / sm_100a).
// The harness also compiles a plain compute_103 pass -> give it a stub body.
#if !defined(__CUDA_ARCH__) || defined(__CUDA_ARCH_FEAT_SM103_ALL) || \
    defined(__CUDA_ARCH_FEAT_SM100_ALL) || defined(__CUDA_ARCH_SPECIFIC__)
#define TC5 1
#else
#define TC5 0
#endif

// ---------------- scratch (no allocs -> device globals) ----------------
// g_deg must be 0 at entry to k_ph: static-init covers call 1; k_mma<2> re-zeros
// at the end of every call (agg2 is the last reader), keeping the invariant
// across CUDA-graph replays.
__device__ int   g_deg[NN];
__device__ int   g_adj[(size_t)NN * MAXDEG];   // slot table: adj[dst*128 + rank]
__device__ __align__(16) float          g_h1[(size_t)NN * DD];   // fp32 (split at mma load)
__device__ __align__(16) __nv_bfloat16  g_mhi[(size_t)NN * DD];
__device__ __align__(16) __nv_bfloat16  g_mlo[(size_t)NN * DD];
__device__ __align__(16) __nv_bfloat16  g_B1hi[DD * 2 * DD];  // [j][k] k-major, K=256
__device__ __align__(16) __nv_bfloat16  g_B1lo[DD * 2 * DD];
__device__ __align__(16) __nv_bfloat16  g_B2hi[DD * 2 * DD];
__device__ __align__(16) __nv_bfloat16  g_B2lo[DD * 2 * DD];

// ---------------- small helpers ----------------
__device__ __forceinline__ uint32_t s2u32(const void* p) {
    uint32_t a;
    asm("{ .reg .u64 t; cvta.to.shared.u64 t, %1; cvt.u32.u64 %0, t; }" : "=r"(a) : "l"(p));
    return a;
}
__device__ __forceinline__ unsigned pk2(__nv_bfloat16 a, __nv_bfloat16 b) {
    unsigned short ua = *(unsigned short*)&a, ub = *(unsigned short*)&b;
    return (unsigned)ua | ((unsigned)ub << 16);
}
__device__ __forceinline__ void split1(float v, __nv_bfloat16& h, __nv_bfloat16& l) {
    h = __float2bfloat16_rn(v);
    l = __float2bfloat16_rn(v - __bfloat162float(h));
}

// ---------------- fused: weight split | slot-table build (one pass, no CSR) ----------------
#define WPREP_BLOCKS 128
#define HIST_BLOCKS  ((NE + 255) / 256)                // 3125
__global__ void k_ph(const void* __restrict__ ei,
                     const float* __restrict__ W1l, const float* __restrict__ W1r,
                     const float* __restrict__ W2l, const float* __restrict__ W2r) {
    int b = blockIdx.x;
    if (b < WPREP_BLOCKS) {
        int id = b * 256 + threadIdx.x;  // < 32768
        int j = id >> 8, k = id & 255;
        float w1 = (k < DD) ? W1l[j * DD + k] : W1r[j * DD + k - DD];
        float w2 = (k < DD) ? W2l[j * DD + k] : W2r[j * DD + k - DD];
        __nv_bfloat16 h, l;
        split1(w1, h, l); g_B1hi[id] = h; g_B1lo[id] = l;
        split1(w2, h, l); g_B2hi[id] = h; g_B2lo[id] = l;
    } else {
        // local edge-dtype detect (JAX x64-off -> int32 likely). If the buffer is
        // int64, every word is a valid node id < NN. If int32, a 64-bit word holds
        // two ids and is >= 2^32 * id_hi (>= NN unless id_hi == 0, p ~ 2e-5/word).
        const unsigned long long* e64 = (const unsigned long long*)ei;
        bool is32 = false;
        #pragma unroll
        for (int k = 0; k < 8; k++)
            if (e64[k] >= (unsigned long long)NN) is32 = true;
        int e = (b - WPREP_BLOCKS) * 256 + threadIdx.x;
        if (e < NE) {
            int dst = is32 ? ((const int*)ei)[NE + e] : (int)((const long long*)ei)[NE + e];
            int src = is32 ? ((const int*)ei)[e]      : (int)((const long long*)ei)[e];
            if ((unsigned)dst < (unsigned)NN && (unsigned)src < (unsigned)NN) {
                int r = atomicAdd(&g_deg[dst], 1);
                if (r < MAXDEG) g_adj[(size_t)dst * MAXDEG + r] = src;
            }
        }
    }
}

// ---------------- mean aggregation: one warp per node; fp32 in, bf16 hi/lo out ----------------
// LAYER selects the feature source ON DEVICE (x param vs g_h1 symbol).
// Packed f32x2 adds: 2 adds per 16B instead of 4 FADD.
template <int LAYER>
__global__ void __launch_bounds__(256) k_agg(const float* __restrict__ x) {
    const float* feat = (LAYER == 1) ? x : (const float*)g_h1;
    int warp = (blockIdx.x * blockDim.x + threadIdx.x) >> 5;
    int lane = threadIdx.x & 31;
    if (warp >= NN) return;
    const int* adjrow = g_adj + (size_t)warp * MAXDEG;
    int d = min(g_deg[warp], MAXDEG);
    unsigned long long a01 = 0ULL, a23 = 0ULL;   // packed f32x2 accumulators
    for (int b = 0; b < d; b += 32) {
        int m  = min(32, d - b);
        int sl = (lane < m) ? adjrow[b + lane] : 0;
        #pragma unroll 4
        for (int j = 0; j < m; j++) {
            int s = __shfl_sync(0xffffffffu, sl, j);
            const ulonglong2 v = __ldg((const ulonglong2*)(feat + (size_t)s * DD) + lane);
            asm("add.rn.f32x2 %0, %0, %1;" : "+l"(a01) : "l"(v.x));
            asm("add.rn.f32x2 %0, %0, %1;" : "+l"(a23) : "l"(v.y));
        }
    }
    float inv = 1.0f / (float)max(d, 1);
    float f0, f1, f2, f3;
    asm("mov.b64 {%0, %1}, %2;" : "=f"(f0), "=f"(f1) : "l"(a01));
    asm("mov.b64 {%0, %1}, %2;" : "=f"(f2), "=f"(f3) : "l"(a23));
    f0 *= inv; f1 *= inv; f2 *= inv; f3 *= inv;
    __nv_bfloat16 h0, h1, h2, h3, l0, l1, l2, l3;
    split1(f0, h0, l0); split1(f1, h1, l1);
    split1(f2, h2, l2); split1(f3, h3, l3);
    size_t rb = (size_t)warp * DD;
    ((uint2*)(g_mhi + rb))[lane] = make_uint2(pk2(h0, h1), pk2(h2, h3));
    ((uint2*)(g_mlo + rb))[lane] = make_uint2(pk2(l0, l1), pk2(l2, l3));
}

// ================= tcgen05 GEMM =================
// Per CTA: 128 rows, N=128, K=256. SS bf16 MMA, fp32 TMEM accum.
// D = Ahi*Bhi + Alo*Bhi + Ahi*Blo  (2-way bf16 split of fp32)
// smem: [1KB slack] A_hi 64KB | A_lo 64KB | B 64KB (Bhi, then Blo via reg preload).
// A left half (cols 0..127) = mean bf16 hi/lo via cp.async.
// A right half (cols 128..255) = fp32 features (x / g_h1) split in registers.
// Layer 1 epilogue writes fp32 h1; layer 2 fuses LayerNorm + re-zeros g_deg.

#define SM_AHI 0
#define SM_ALO 65536
#define SM_B   131072
#define DSMEM  (196608 + 1024)

static constexpr uint32_t IDESC_BF16 =
    (1u << 4) | (1u << 7) | (1u << 10) | ((128u / 8) << 17) | ((128u / 16) << 24);

// blocked SW128 atom layout: atom = 8 rows x 64 bf16 (1024B); 16 atom-rows, 4 atom-cols
__device__ __forceinline__ int sw_chunk(int row, int col) {   // col multiple of 8
    int byte = ((row >> 3) + (col >> 6) * 16) * 1024 + (row & 7) * 128 + (col & 63) * 2;
    return byte ^ ((byte >> 3) & 0x70);
}
__device__ __forceinline__ uint64_t mk_desc(uint32_t addr) {
    const uint64_t base = (2ull << 61) | (1ull << 46) | (64ull << 32) | (1ull << 16);
    return base | ((uint64_t)(addr >> 4) & 0x3FFF);
}
__device__ __forceinline__ uint64_t koff(int t) {   // K16-step t=0..15
    return (uint64_t)(((t >> 2) * 1024) + (t & 3) * 2);
}

#if TC5
__device__ __forceinline__ void mma_bf16_ss(uint32_t d, uint64_t ad, uint64_t bd,
                                            uint32_t en) {
    asm volatile(
        "{\n\t.reg .pred p;\n\tsetp.ne.u32 p, %4, 0;\n\t"
        "tcgen05.mma.cta_group::1.kind::f16 [%0], %1, %2, %3, {%5, %5, %5, %5}, p;\n\t}"
        :: "r"(d), "l"(ad), "l"(bd), "r"(IDESC_BF16), "r"(en), "r"(0u) : "memory");
}
__device__ __forceinline__ void cp16(uint32_t saddr, const void* gaddr) {
    asm volatile("cp.async.cg.shared.global [%0], [%1], 16;"
                 :: "r"(saddr), "l"(gaddr) : "memory");
}
#endif
__device__ __forceinline__ void mbar_wait(uint32_t mbar, uint32_t parity) {
    uint32_t done;
    asm volatile(
        "{\n\t.reg .pred p;\n\t"
        "mbarrier.try_wait.parity.acquire.cta.shared::cta.b64 p, [%1], %2;\n\t"
        "selp.b32 %0, 1, 0, p;\n\t}"
        : "=r"(done) : "r"(mbar), "r"(parity) : "memory");
    if (!done) {
        asm volatile(
            "{\n\t.reg .pred P1;\n\t"
            "WL_%=:\n\t"
            "mbarrier.try_wait.parity.acquire.cta.shared::cta.b64 P1, [%0], %1, 0x989680;\n\t"
            "@P1 bra.uni WD_%=;\n\t"
            "bra.uni WL_%=;\n\t"
            "WD_%=:\n\t}"
            :: "r"(mbar), "r"(parity) : "memory");
    }
}

template <int LAYER>
__global__ void __launch_bounds__(256) k_mma(
    const float* __restrict__ xin, const float* __restrict__ bias,
    const float* __restrict__ lnw, const float* __restrict__ lnb,
    float* __restrict__ outp)
{
#if TC5
    extern __shared__ char dsm_raw[];
    __shared__ uint32_t s_tmem;
    __shared__ __align__(8) unsigned long long s_mbar;
    __shared__ float sb[DD], slw[DD], slb[DD];
    __shared__ float psS[2][DD], psQ[2][DD];

    const uint32_t raw_u = s2u32(dsm_raw);
    const uint32_t dsm_u = (raw_u + 1023u) & ~1023u;   // SW128 needs 1KB-aligned base
    char* dsm = dsm_raw + (dsm_u - raw_u);

    const int tid  = threadIdx.x;
    const int wid  = tid >> 5;
    const int lane = tid & 31;
    const int row0 = blockIdx.x * 128;

    const float* hsrc = (LAYER == 1) ? xin : (const float*)g_h1;
    const __nv_bfloat16* Bhi = (LAYER == 1) ? g_B1hi : g_B2hi;
    const __nv_bfloat16* Blo = (LAYER == 1) ? g_B1lo : g_B2lo;

    uint32_t mbar_a = s2u32(&s_mbar);
    uint32_t tmslot = s2u32(&s_tmem);

    if (wid == 0) {
        asm volatile(
            "tcgen05.alloc.cta_group::1.sync.aligned.shared::cta.b32 [%0], %1;"
            :: "r"(tmslot), "r"(128u) : "memory");
    }
    if (tid == 0)
        asm volatile("mbarrier.init.shared.b64 [%0], %1;" :: "r"(mbar_a), "r"(1u) : "memory");
    if (tid < DD) {
        sb[tid] = bias[tid];
        if (LAYER == 2) { slw[tid] = lnw[tid]; slb[tid] = lnb[tid]; }
    }

    // Layer 2: re-zero g_deg for the next call (agg2 was the last reader; this
    // kernel is stream-ordered after it). Grid 391*256 covers NN.
    if (LAYER == 2) {
        int zi = blockIdx.x * 256 + tid;
        if (zi < NN) g_deg[zi] = 0;
    }

    // ---- chunk map: 16 chunks/thread of 16B; row=c>>5, col=(c&31)*8 ----
    int rr[16], cc[16], so[16];
    #pragma unroll
    for (int it = 0; it < 16; it++) {
        int c = tid + it * 256;
        rr[it] = c >> 5; cc[it] = (c & 31) * 8;
        so[it] = sw_chunk(rr[it], cc[it]);
    }

    // group 1: B(hi) + mean-hi (left half)
    #pragma unroll
    for (int it = 0; it < 16; it++)
        cp16(dsm_u + SM_B + so[it], Bhi + rr[it] * 256 + cc[it]);
    #pragma unroll
    for (int it = 0; it < 16; it++) {
        if (cc[it] < DD) {
            int gr = row0 + rr[it]; if (gr >= NN) gr = 0;   // clamp: rows never stored
            cp16(dsm_u + SM_AHI + so[it], g_mhi + (size_t)gr * DD + cc[it]);
        }
    }
    asm volatile("cp.async.commit_group;" ::: "memory");     // group: B + mean-hi
    #pragma unroll
    for (int it = 0; it < 16; it++) {
        if (cc[it] < DD) {
            int gr = row0 + rr[it]; if (gr >= NN) gr = 0;
            cp16(dsm_u + SM_ALO + so[it], g_mlo + (size_t)gr * DD + cc[it]);
        }
    }
    asm volatile("cp.async.commit_group;" ::: "memory");     // group: mean-lo

    // right half: fp32 features, split in registers, STS to both buffers
    #pragma unroll
    for (int it = 0; it < 16; it++) {
        if (cc[it] >= DD) {
            int gr = row0 + rr[it]; if (gr >= NN) gr = 0;
            const float* xr = hsrc + (size_t)gr * DD + (cc[it] - DD);
            float4 a = *(const float4*)xr;
            float4 b = *(const float4*)(xr + 4);
            __nv_bfloat16 h[8], l[8];
            split1(a.x, h[0], l[0]); split1(a.y, h[1], l[1]);
            split1(a.z, h[2], l[2]); split1(a.w, h[3], l[3]);
            split1(b.x, h[4], l[4]); split1(b.y, h[5], l[5]);
            split1(b.z, h[6], l[6]); split1(b.w, h[7], l[7]);
            *(uint4*)(dsm + SM_AHI + so[it]) =
                make_uint4(pk2(h[0],h[1]), pk2(h[2],h[3]), pk2(h[4],h[5]), pk2(h[6],h[7]));
            *(uint4*)(dsm + SM_ALO + so[it]) =
                make_uint4(pk2(l[0],l[1]), pk2(l[2],l[3]), pk2(l[4],l[5]), pk2(l[6],l[7]));
        }
    }

    __syncthreads();   // alloc + mbar init visible
    uint32_t tmem;
    asm volatile("ld.shared.b32 %0, [%1];" : "=r"(tmem) : "r"(tmslot));

    uint64_t dAhi = mk_desc(dsm_u + SM_AHI);
    uint64_t dAlo = mk_desc(dsm_u + SM_ALO);
    uint64_t dB   = mk_desc(dsm_u + SM_B);

    // ---- phase A1: Ahi*Bhi (mean-lo may still be streaming) ----
    asm volatile("cp.async.wait_group 1;" ::: "memory");
    __syncthreads();
    if (tid == 0) {
        asm volatile("fence.proxy.async.shared::cta;" ::: "memory");
        #pragma unroll
        for (int t = 0; t < 16; t++)
            mma_bf16_ss(tmem, dAhi + koff(t), dB + koff(t), t > 0);
    }
    // ---- phase A2: Alo*Bhi ----
    asm volatile("cp.async.wait_group 0;" ::: "memory");
    __syncthreads();
    if (tid == 0) {
        asm volatile("fence.proxy.async.shared::cta;" ::: "memory");
        #pragma unroll
        for (int t = 0; t < 16; t++)
            mma_bf16_ss(tmem, dAlo + koff(t), dB + koff(t), 1);
        asm volatile(
            "tcgen05.commit.cta_group::1.mbarrier::arrive::one.shared::cluster.b64 [%0];"
            :: "r"(mbar_a) : "memory");
    }

    // ---- preload Blo into registers under the phase-A shadow ----
    uint4 bl[16];
    #pragma unroll
    for (int it = 0; it < 16; it++)
        bl[it] = *(const uint4*)(Blo + rr[it] * 256 + cc[it]);

    mbar_wait(mbar_a, 0);

    // ---- swap B -> Blo (STS only) ----
    #pragma unroll
    for (int it = 0; it < 16; it++)
        *(uint4*)(dsm + SM_B + so[it]) = bl[it];
    __syncthreads();

    // ---- phase B: Ahi*Blo ----
    if (tid == 0) {
        asm volatile("fence.proxy.async.shared::cta;" ::: "memory");
        #pragma unroll
        for (int t = 0; t < 16; t++)
            mma_bf16_ss(tmem, dAhi + koff(t), dB + koff(t), 1);
        asm volatile(
            "tcgen05.commit.cta_group::1.mbarrier::arrive::one.shared::cluster.b64 [%0];"
            :: "r"(mbar_a) : "memory");
    }
    mbar_wait(mbar_a, 1);
    asm volatile("tcgen05.fence::after_thread_sync;" ::: "memory");

    // ---- epilogue: warp w -> rows (w&3)*32+lane, cols (w>>2)*64..+63 ----
    const int sub = wid & 3, half = wid >> 2;
    const int cb = half * 64;
    uint32_t dr[64];
    #define LD32(p, a) \
        asm volatile("tcgen05.ld.sync.aligned.32x32b.x32.b32 " \
            "{%0,%1,%2,%3,%4,%5,%6,%7,%8,%9,%10,%11,%12,%13,%14,%15," \
            "%16,%17,%18,%19,%20,%21,%22,%23,%24,%25,%26,%27,%28,%29,%30,%31}, [%32];" \
            : "=r"((p)[0]),"=r"((p)[1]),"=r"((p)[2]),"=r"((p)[3]),"=r"((p)[4]),"=r"((p)[5]), \
              "=r"((p)[6]),"=r"((p)[7]),"=r"((p)[8]),"=r"((p)[9]),"=r"((p)[10]),"=r"((p)[11]), \
              "=r"((p)[12]),"=r"((p)[13]),"=r"((p)[14]),"=r"((p)[15]),"=r"((p)[16]),"=r"((p)[17]), \
              "=r"((p)[18]),"=r"((p)[19]),"=r"((p)[20]),"=r"((p)[21]),"=r"((p)[22]),"=r"((p)[23]), \
              "=r"((p)[24]),"=r"((p)[25]),"=r"((p)[26]),"=r"((p)[27]),"=r"((p)[28]),"=r"((p)[29]), \
              "=r"((p)[30]),"=r"((p)[31]) : "r"(a))
    LD32(dr,      tmem + cb);
    LD32(dr + 32, tmem + cb + 32);
    asm volatile("tcgen05.wait::ld.sync.aligned;" ::: "memory");
    #undef LD32

    const int r = sub * 32 + lane;          // local row
    const int gr = row0 + r;
    float v[64];
    float s = 0.f, sq = 0.f;
    #pragma unroll
    for (int j = 0; j < 64; j++) {
        float f = fmaxf(__uint_as_float(dr[j]) + sb[cb + j], 0.f);
        v[j] = f;
        s += f; sq += f * f;
    }

    if (LAYER == 1) {
        if (gr < NN) {
            size_t rbase = (size_t)gr * DD + cb;
            #pragma unroll
            for (int c4 = 0; c4 < 16; c4++)
                *(float4*)(g_h1 + rbase + c4 * 4) =
                    make_float4(v[c4*4+0], v[c4*4+1], v[c4*4+2], v[c4*4+3]);
        }
    } else {
        psS[half][r] = s;
        psQ[half][r] = sq;
        __syncthreads();
        float st = psS[0][r] + psS[1][r];
        float qt = psQ[0][r] + psQ[1][r];
        float mu  = st * (1.0f / DD);
        float var = qt * (1.0f / DD) - mu * mu;
        float rs  = rsqrtf(var + 1e-5f);
        if (gr < NN) {
            size_t rbase = (size_t)gr * DD + cb;
            #pragma unroll
            for (int c4 = 0; c4 < 16; c4++) {
                float4 o;
                o.x = (v[c4*4+0] - mu) * rs * slw[cb+c4*4+0] + slb[cb+c4*4+0];
                o.y = (v[c4*4+1] - mu) * rs * slw[cb+c4*4+1] + slb[cb+c4*4+1];
                o.z = (v[c4*4+2] - mu) * rs * slw[cb+c4*4+2] + slb[cb+c4*4+2];
                o.w = (v[c4*4+3] - mu) * rs * slw[cb+c4*4+3] + slb[cb+c4*4+3];
                *(float4*)(outp + rbase + c4 * 4) = o;
            }
        }
    }

    __syncthreads();
    if (tid == 0)
        asm volatile("mbarrier.inval.shared.b64 [%0];" :: "r"(mbar_a) : "memory");
    __syncthreads();
    if (wid == 0) {
        asm volatile("tcgen05.dealloc.cta_group::1.sync.aligned.b32 %0, %1;"
                     :: "r"(tmem), "r"(128u));
        asm volatile("tcgen05.relinquish_alloc_permit.cta_group::1.sync.aligned;");
    }
#endif  // TC5
}

// ---------------- launch ----------------
extern "C" void kernel_launch(void* const* d_in, const int* in_sizes, int n_in,
                              void* d_out, int out_size) {
    const float* x   = (const float*)d_in[0];
    const void*  ei  = d_in[1];
    const float* W1l = (const float*)d_in[2];
    const float* b1l = (const float*)d_in[3];
    const float* W1r = (const float*)d_in[4];
    const float* W2l = (const float*)d_in[5];
    const float* b2l = (const float*)d_in[6];
    const float* W2r = (const float*)d_in[7];
    const float* lnw = (const float*)d_in[8];
    const float* lnb = (const float*)d_in[9];
    float* out = (float*)d_out;

    cudaFuncSetAttribute(k_mma<1>, cudaFuncAttributeMaxDynamicSharedMemorySize, DSMEM);
    cudaFuncSetAttribute(k_mma<2>, cudaFuncAttributeMaxDynamicSharedMemorySize, DSMEM);

    const int ph_blocks  = WPREP_BLOCKS + HIST_BLOCKS;
    const int mma_blocks = (NN + 127) / 128;                    // 391

    // single-pass adjacency build (slot table, no CSR)
    k_ph<<<ph_blocks, 256>>>(ei, W1l, W1r, W2l, W2r);

    // layer 1
    k_agg<1><<<(NN * 32 + 255) / 256, 256>>>(x);
    k_mma<1><<<mma_blocks, 256, DSMEM>>>(x, b1l, nullptr, nullptr, out);

    // layer 2 (+ LayerNorm; re-zeros g_deg for next call)
    k_agg<2><<<(NN * 32 + 255) / 256, 256>>>(x);
    k_mma<2><<<mma_blocks, 256, DSMEM>>>(x, b2l, lnw, lnb, out);
}